// round 11
// baseline (speedup 1.0000x reference)
#include <cuda_runtime.h>
#include <cuda_fp16.h>
#include <cstdint>

#define NN    50000
#define EE    800000
#define HH    128
#define GG    128
#define OUTD  10
#define NHOPS 4
#define NB    ((NN + 255) / 256)   // 196 scan blocks

// ---------------- device scratch (static, no runtime allocation) ----------------
__device__ __align__(16) float  d_h0[NN * HH];
__device__ __align__(16) float  d_h1[NN * HH];
__device__ __align__(16) __half d_g[NN * HH];    // fp16 gather buffer
__device__ float d_dinv[NN];
__device__ int   d_degcnt[NN];
__device__ int   d_rowptr[NN + 1];
__device__ int   d_cursor[NN];
__device__ int   d_esrc[EE];
__device__ float d_sums[GG * OUTD];
__device__ float d_cnt[GG];
__device__ int   d_stride;     // 1 = int32 inputs, 2 = int64 inputs
__device__ int   d_blksum[NB];
__device__ int   d_blkoff[NB];

__device__ __forceinline__ int clampi(int v, int lo, int hi) {
    return v < lo ? lo : (v > hi ? hi : v);
}

__device__ __forceinline__ uint32_t f2tf(float f) {
    uint32_t u;
    asm("cvt.rna.tf32.f32 %0, %1;" : "=r"(u) : "f"(f));
    return u;
}

// ---------------- dtype detection: int32 vs int64 edge_index -------------------
__global__ void detect_kernel(const int* __restrict__ ei_words) {
    __shared__ int nonzero;
    if (threadIdx.x == 0) nonzero = 0;
    __syncthreads();
    int w = ei_words[2 * threadIdx.x + 1];
    if (w != 0) atomicOr(&nonzero, 1);
    __syncthreads();
    if (threadIdx.x == 0) d_stride = nonzero ? 1 : 2;
}

// ---------------- zero per-launch state ----------------
__global__ void zero_kernel() {
    int i = blockIdx.x * blockDim.x + threadIdx.x;
    if (i < NN) { d_degcnt[i] = 0; d_cursor[i] = 0; }
    if (i < GG * OUTD) d_sums[i] = 0.0f;
    if (i < GG) d_cnt[i] = 0.0f;
}

// ---------------- in-degree count ----------------
__global__ void count_kernel(const int* __restrict__ ei) {
    int e = blockIdx.x * blockDim.x + threadIdx.x;
    if (e < EE) {
        int st = d_stride;
        int dst = clampi(ei[(size_t)st * (EE + e)], 0, NN - 1);
        atomicAdd(&d_degcnt[dst], 1);
    }
}

// ---------------- scan stages ----------------
__global__ __launch_bounds__(256) void scanA_kernel() {
    int i = blockIdx.x * 256 + threadIdx.x;
    int v = (i < NN) ? d_degcnt[i] : 0;
    int lane = threadIdx.x & 31, wid = threadIdx.x >> 5;
    int s = v;
    #pragma unroll
    for (int o = 16; o > 0; o >>= 1) s += __shfl_down_sync(0xffffffffu, s, o);
    __shared__ int ws[8];
    if (lane == 0) ws[wid] = s;
    __syncthreads();
    if (threadIdx.x == 0) {
        int t = 0;
        #pragma unroll
        for (int w = 0; w < 8; w++) t += ws[w];
        d_blksum[blockIdx.x] = t;
    }
}

__global__ __launch_bounds__(256) void scanB_kernel() {
    __shared__ int s_a[256], s_b[256];
    int t = threadIdx.x;
    int v = (t < NB) ? d_blksum[t] : 0;
    s_a[t] = v;
    __syncthreads();
    int* cur = s_a; int* nxt = s_b;
    for (int off = 1; off < 256; off <<= 1) {
        int x = cur[t];
        if (t >= off) x += cur[t - off];
        nxt[t] = x;
        __syncthreads();
        int* tmp = cur; cur = nxt; nxt = tmp;
    }
    if (t < NB) d_blkoff[t] = cur[t] - v;
    if (t == 0) d_rowptr[NN] = EE;
}

__global__ __launch_bounds__(256) void scanC_kernel() {
    int i = blockIdx.x * 256 + threadIdx.x;
    int v = (i < NN) ? d_degcnt[i] : 0;
    int lane = threadIdx.x & 31, wid = threadIdx.x >> 5;
    int incl = v;
    #pragma unroll
    for (int o = 1; o < 32; o <<= 1) {
        int y = __shfl_up_sync(0xffffffffu, incl, o);
        if (lane >= o) incl += y;
    }
    __shared__ int ws[8];
    if (lane == 31) ws[wid] = incl;
    __syncthreads();
    int woff = 0;
    #pragma unroll
    for (int w = 0; w < 8; w++) woff += (w < wid) ? ws[w] : 0;
    if (i < NN) {
        d_rowptr[i] = d_blkoff[blockIdx.x] + woff + incl - v;
        d_dinv[i] = rsqrtf(1.0f + (float)v);
    }
}

// ---------------- scatter edges into CSR buckets ----------------
__global__ void scatter_kernel(const int* __restrict__ ei) {
    int e = blockIdx.x * blockDim.x + threadIdx.x;
    if (e < EE) {
        int st = d_stride;
        int dst = clampi(ei[(size_t)st * (EE + e)], 0, NN - 1);
        int src = clampi(ei[(size_t)st * e],        0, NN - 1);
        int pos = d_rowptr[dst] + atomicAdd(&d_cursor[dst], 1);
        if (pos >= 0 && pos < EE) d_esrc[pos] = src;
    }
}

// ---------------- TF32 tensor-core GEMM (R9 design) ---------------------------
// C = (A @ B + bias) * scale.  csel==0 -> writes d_g as fp16; else fp32 h buffer.
__global__ __launch_bounds__(256) void gemm_tf32_kernel(
    const float* __restrict__ Aext, const float* __restrict__ B,
    const float* __restrict__ bias, int asel, int use_scale, int csel)
{
    __shared__ float As[64 * 132];   // 33792 B
    __shared__ float Bs[16 * 136];   //  8704 B

    const float* A = (asel == 0) ? Aext : (asel == 1 ? d_h0 : d_h1);
    float* C = (csel == 1) ? d_h0 : d_h1;   // fp32 targets only

    int tid = threadIdx.x;
    int wid = tid >> 5, lane = tid & 31;
    int g = lane >> 2, t = lane & 3;
    int wm = wid & 1, wn = wid >> 1;     // warp grid 2 x 4
    int row0 = blockIdx.x * 64;

    {
        float4* As4 = (float4*)As;          // float4 stride = 33
        const float4* A4 = (const float4*)A;
        #pragma unroll
        for (int i = 0; i < 8; i++) {
            int idx = i * 256 + tid;
            int r = idx >> 5, c = idx & 31;
            int gr = row0 + r;
            As4[r * 33 + c] = (gr < NN) ? A4[(size_t)gr * 32 + c]
                                        : make_float4(0.f, 0.f, 0.f, 0.f);
        }
    }

    float acc[2][4][4];
    #pragma unroll
    for (int am = 0; am < 2; am++)
        #pragma unroll
        for (int an = 0; an < 4; an++)
            #pragma unroll
            for (int q = 0; q < 4; q++) acc[am][an][q] = 0.0f;

    const float4* B4 = (const float4*)B;
    float4* Bs4 = (float4*)Bs;              // float4 stride = 34

    for (int kc = 0; kc < 8; kc++) {
        __syncthreads();
        #pragma unroll
        for (int i = 0; i < 2; i++) {
            int idx = i * 256 + tid;
            int r = idx >> 5, c = idx & 31;
            Bs4[r * 34 + c] = B4[(size_t)(kc * 16 + r) * 32 + c];
        }
        __syncthreads();

        #pragma unroll
        for (int ka = 0; ka < 2; ka++) {
            int kcol = kc * 16 + ka * 8;
            int kb = ka * 8;

            uint32_t a[2][4];
            #pragma unroll
            for (int am = 0; am < 2; am++) {
                int ar = wm * 32 + am * 16;
                const float* Ap = As + (size_t)(ar + g) * 132 + kcol + t;
                a[am][0] = f2tf(Ap[0]);
                a[am][1] = f2tf(Ap[8 * 132]);
                a[am][2] = f2tf(Ap[4]);
                a[am][3] = f2tf(Ap[8 * 132 + 4]);
            }
            uint32_t b[4][2];
            #pragma unroll
            for (int an = 0; an < 4; an++) {
                int bc = wn * 32 + an * 8 + g;
                b[an][0] = f2tf(Bs[(size_t)(kb + t) * 136 + bc]);
                b[an][1] = f2tf(Bs[(size_t)(kb + t + 4) * 136 + bc]);
            }
            #pragma unroll
            for (int am = 0; am < 2; am++)
                #pragma unroll
                for (int an = 0; an < 4; an++) {
                    asm volatile(
                        "mma.sync.aligned.m16n8k8.row.col.f32.tf32.tf32.f32 "
                        "{%0,%1,%2,%3}, {%4,%5,%6,%7}, {%8,%9}, {%0,%1,%2,%3};"
                        : "+f"(acc[am][an][0]), "+f"(acc[am][an][1]),
                          "+f"(acc[am][an][2]), "+f"(acc[am][an][3])
                        : "r"(a[am][0]), "r"(a[am][1]), "r"(a[am][2]), "r"(a[am][3]),
                          "r"(b[an][0]), "r"(b[an][1]));
                }
        }
    }

    // epilogue: c0:(g,2t) c1:(g,2t+1) c2:(g+8,2t) c3:(g+8,2t+1)
    __half2* Gh = (__half2*)d_g;
    #pragma unroll
    for (int am = 0; am < 2; am++) {
        int r0a = row0 + wm * 32 + am * 16;
        int rA = r0a + g;
        int rB = r0a + g + 8;
        float sA = 1.0f, sB = 1.0f;
        if (use_scale) {
            if (rA < NN) sA = d_dinv[rA];
            if (rB < NN) sB = d_dinv[rB];
        }
        #pragma unroll
        for (int an = 0; an < 4; an++) {
            int col = wn * 32 + an * 8 + 2 * t;
            float bx = bias ? bias[col]     : 0.0f;
            float by = bias ? bias[col + 1] : 0.0f;
            if (rA < NN) {
                float ox = (acc[am][an][0] + bx) * sA;
                float oy = (acc[am][an][1] + by) * sA;
                if (csel == 0) Gh[((size_t)rA * HH + col) >> 1] = __floats2half2_rn(ox, oy);
                else *(float2*)(C + (size_t)rA * HH + col) = make_float2(ox, oy);
            }
            if (rB < NN) {
                float ox = (acc[am][an][2] + bx) * sB;
                float oy = (acc[am][an][3] + by) * sB;
                if (csel == 0) Gh[((size_t)rB * HH + col) >> 1] = __floats2half2_rn(ox, oy);
                else *(float2*)(C + (size_t)rB * HH + col) = make_float2(ox, oy);
            }
        }
    }
}

// ---------------- neighborhood aggregation (warp per node, fp16 gather) --------
// Row = 128 halves = 32 uint2; lane loads uint2 (4 halves = its 4 cols).
__global__ __launch_bounds__(256) void aggregate_kernel(
    const float* __restrict__ bias, int relu, int outsel)
{
    int node = blockIdx.x * 8 + (threadIdx.x >> 5);
    if (node >= NN) return;
    int lane = threadIdx.x & 31;
    float* out = (outsel == 1) ? d_h0 : d_h1;

    const uint2* g2 = (const uint2*)d_g;

    float4 acc;
    {
        uint2 u = g2[(size_t)node * 32 + lane];     // self term
        float2 f0 = __half22float2(*(__half2*)&u.x);
        float2 f1 = __half22float2(*(__half2*)&u.y);
        acc.x = f0.x; acc.y = f0.y; acc.z = f1.x; acc.w = f1.y;
    }

    int s = d_rowptr[node], e = d_rowptr[node + 1];
    int j = s;
    for (; j + 3 < e; j += 4) {
        int s0 = d_esrc[j], s1 = d_esrc[j + 1], s2 = d_esrc[j + 2], s3 = d_esrc[j + 3];
        uint2 u0 = g2[(size_t)s0 * 32 + lane];
        uint2 u1 = g2[(size_t)s1 * 32 + lane];
        uint2 u2 = g2[(size_t)s2 * 32 + lane];
        uint2 u3 = g2[(size_t)s3 * 32 + lane];
        float2 a0 = __half22float2(*(__half2*)&u0.x), b0 = __half22float2(*(__half2*)&u0.y);
        float2 a1 = __half22float2(*(__half2*)&u1.x), b1 = __half22float2(*(__half2*)&u1.y);
        float2 a2 = __half22float2(*(__half2*)&u2.x), b2 = __half22float2(*(__half2*)&u2.y);
        float2 a3 = __half22float2(*(__half2*)&u3.x), b3 = __half22float2(*(__half2*)&u3.y);
        acc.x += a0.x + a1.x + a2.x + a3.x;
        acc.y += a0.y + a1.y + a2.y + a3.y;
        acc.z += b0.x + b1.x + b2.x + b3.x;
        acc.w += b0.y + b1.y + b2.y + b3.y;
    }
    for (; j < e; j++) {
        uint2 u = g2[(size_t)d_esrc[j] * 32 + lane];
        float2 f0 = __half22float2(*(__half2*)&u.x);
        float2 f1 = __half22float2(*(__half2*)&u.y);
        acc.x += f0.x; acc.y += f0.y; acc.z += f1.x; acc.w += f1.y;
    }

    float di = d_dinv[node];
    float4 b4 = ((const float4*)bias)[lane];
    float4 o;
    o.x = fmaf(acc.x, di, b4.x);
    o.y = fmaf(acc.y, di, b4.y);
    o.z = fmaf(acc.z, di, b4.z);
    o.w = fmaf(acc.w, di, b4.w);
    if (relu) {
        o.x = fmaxf(o.x, 0.f); o.y = fmaxf(o.y, 0.f);
        o.z = fmaxf(o.z, 0.f); o.w = fmaxf(o.w, 0.f);
    }
    ((float4*)out)[(size_t)node * 32 + lane] = o;
}

// ---------------- fused last-hop aggregation + classifier + pool ----------------
__global__ __launch_bounds__(256) void aggregate_cls_kernel(
    const float* __restrict__ bias, const int* __restrict__ batch,
    const float* __restrict__ Wc, const float* __restrict__ bc)
{
    __shared__ float sW[HH * OUTD];
    __shared__ float sB[OUTD];
    int tid = threadIdx.x;
    for (int i = tid; i < HH * OUTD; i += 256) sW[i] = Wc[i];
    if (tid < OUTD) sB[tid] = bc[tid];
    __syncthreads();

    int node = blockIdx.x * 8 + (tid >> 5);
    if (node >= NN) return;
    int lane = tid & 31;

    const uint2* g2 = (const uint2*)d_g;

    float4 acc;
    {
        uint2 u = g2[(size_t)node * 32 + lane];
        float2 f0 = __half22float2(*(__half2*)&u.x);
        float2 f1 = __half22float2(*(__half2*)&u.y);
        acc.x = f0.x; acc.y = f0.y; acc.z = f1.x; acc.w = f1.y;
    }

    int s = d_rowptr[node], e = d_rowptr[node + 1];
    int j = s;
    for (; j + 3 < e; j += 4) {
        int s0 = d_esrc[j], s1 = d_esrc[j + 1], s2 = d_esrc[j + 2], s3 = d_esrc[j + 3];
        uint2 u0 = g2[(size_t)s0 * 32 + lane];
        uint2 u1 = g2[(size_t)s1 * 32 + lane];
        uint2 u2 = g2[(size_t)s2 * 32 + lane];
        uint2 u3 = g2[(size_t)s3 * 32 + lane];
        float2 a0 = __half22float2(*(__half2*)&u0.x), b0 = __half22float2(*(__half2*)&u0.y);
        float2 a1 = __half22float2(*(__half2*)&u1.x), b1 = __half22float2(*(__half2*)&u1.y);
        float2 a2 = __half22float2(*(__half2*)&u2.x), b2 = __half22float2(*(__half2*)&u2.y);
        float2 a3 = __half22float2(*(__half2*)&u3.x), b3 = __half22float2(*(__half2*)&u3.y);
        acc.x += a0.x + a1.x + a2.x + a3.x;
        acc.y += a0.y + a1.y + a2.y + a3.y;
        acc.z += b0.x + b1.x + b2.x + b3.x;
        acc.w += b0.y + b1.y + b2.y + b3.y;
    }
    for (; j < e; j++) {
        uint2 u = g2[(size_t)d_esrc[j] * 32 + lane];
        float2 f0 = __half22float2(*(__half2*)&u.x);
        float2 f1 = __half22float2(*(__half2*)&u.y);
        acc.x += f0.x; acc.y += f0.y; acc.z += f1.x; acc.w += f1.y;
    }

    float di = d_dinv[node];
    float4 b4 = ((const float4*)bias)[lane];
    float4 o;                      // cols 4*lane .. 4*lane+3 (no relu on last hop)
    o.x = fmaf(acc.x, di, b4.x);
    o.y = fmaf(acc.y, di, b4.y);
    o.z = fmaf(acc.z, di, b4.z);
    o.w = fmaf(acc.w, di, b4.w);

    int c0 = 4 * lane;
    float p[OUTD];
    #pragma unroll
    for (int d = 0; d < OUTD; d++) {
        float v = o.x * sW[(c0 + 0) * OUTD + d];
        v = fmaf(o.y, sW[(c0 + 1) * OUTD + d], v);
        v = fmaf(o.z, sW[(c0 + 2) * OUTD + d], v);
        v = fmaf(o.w, sW[(c0 + 3) * OUTD + d], v);
        p[d] = v;
    }
    #pragma unroll
    for (int off = 16; off > 0; off >>= 1) {
        #pragma unroll
        for (int d = 0; d < OUTD; d++)
            p[d] += __shfl_xor_sync(0xffffffffu, p[d], off);
    }
    int st = d_stride;
    int b = clampi(batch[(size_t)st * node], 0, GG - 1);
    if (lane < OUTD) {
        float v = p[0];
        #pragma unroll
        for (int d = 1; d < OUTD; d++) v = (lane == d) ? p[d] : v;
        atomicAdd(&d_sums[b * OUTD + lane], v + sB[lane]);
    }
    if (lane == OUTD) atomicAdd(&d_cnt[b], 1.0f);
}

// ---------------- final divide ----------------
__global__ void finalize_kernel(float* __restrict__ out) {
    int i = blockIdx.x * blockDim.x + threadIdx.x;
    if (i < GG * OUTD) {
        float c = d_cnt[i / OUTD];
        out[i] = d_sums[i] / fmaxf(c, 1.0f);
    }
}

// ---------------- launch ----------------
extern "C" void kernel_launch(void* const* d_in, const int* in_sizes, int n_in,
                              void* d_out, int out_size) {
    const float* x      = (const float*)d_in[0];
    const int*   ei     = (const int*)d_in[1];
    const int*   batch  = (const int*)d_in[2];
    const float* W_in   = (const float*)d_in[3];
    const float* b_in   = (const float*)d_in[4];
    const float* W_hops = (const float*)d_in[5];
    const float* b_hops = (const float*)d_in[6];
    const float* W_cls  = (const float*)d_in[7];
    const float* b_cls  = (const float*)d_in[8];
    float* out = (float*)d_out;

    const int GB = (NN + 63) / 64;

    detect_kernel<<<1, 128>>>(ei);
    zero_kernel<<<(NN + 255) / 256, 256>>>();
    count_kernel<<<(EE + 255) / 256, 256>>>(ei);
    // encoder GEMM in slot 4 for stable ncu sampling (writes fp32 h0)
    gemm_tf32_kernel<<<GB, 256>>>(x, W_in, b_in, 0, 0, 1);
    scanA_kernel<<<NB, 256>>>();
    scanB_kernel<<<1, 256>>>();
    scanC_kernel<<<NB, 256>>>();
    scatter_kernel<<<(EE + 255) / 256, 256>>>(ei);

    int cur = 1;   // d_h0
    for (int hop = 0; hop < NHOPS; hop++) {
        int nxt = (cur == 1) ? 2 : 1;
        // d_g(half) = (h_cur @ W_hop) * dinv[row]
        gemm_tf32_kernel<<<GB, 256>>>(nullptr, W_hops + (size_t)hop * HH * HH,
                                      nullptr, cur, 1, 0);
        if (hop < NHOPS - 1) {
            aggregate_kernel<<<(NN + 7) / 8, 256>>>(b_hops + hop * HH, 1, nxt);
        } else {
            aggregate_cls_kernel<<<(NN + 7) / 8, 256>>>(b_hops + hop * HH,
                                                        batch, W_cls, b_cls);
        }
        cur = nxt;
    }

    finalize_kernel<<<(GG * OUTD + 255) / 256, 256>>>(out);
}

// round 12
// speedup vs baseline: 1.3912x; 1.3912x over previous
#include <cuda_runtime.h>
#include <cstdint>

#define NN    50000
#define EE    800000
#define HH    128
#define GG    128
#define OUTD  10
#define NHOPS 4
#define NB    ((NN + 255) / 256)   // 196 scan blocks

// ---------------- device scratch (static, no runtime allocation) ----------------
__device__ __align__(16) float d_h0[NN * HH];
__device__ __align__(16) float d_h1[NN * HH];
__device__ __align__(16) float d_g[NN * HH];
__device__ float d_dinv[NN];
__device__ int   d_degcnt[NN];
__device__ int   d_rowptr[NN + 1];
__device__ int   d_cursor[NN];
__device__ int   d_esrc[EE];
__device__ float d_sums[GG * OUTD];
__device__ float d_cnt[GG];
__device__ int   d_stride;     // 1 = int32 inputs, 2 = int64 inputs
__device__ int   d_blksum[NB];
__device__ int   d_blkoff[NB];

__device__ __forceinline__ int clampi(int v, int lo, int hi) {
    return v < lo ? lo : (v > hi ? hi : v);
}

__device__ __forceinline__ uint32_t f2tf(float f) {
    uint32_t u;
    asm("cvt.rna.tf32.f32 %0, %1;" : "=r"(u) : "f"(f));
    return u;
}

// ---------------- dtype detection: int32 vs int64 edge_index -------------------
__global__ void detect_kernel(const int* __restrict__ ei_words) {
    __shared__ int nonzero;
    if (threadIdx.x == 0) nonzero = 0;
    __syncthreads();
    int w = ei_words[2 * threadIdx.x + 1];
    if (w != 0) atomicOr(&nonzero, 1);
    __syncthreads();
    if (threadIdx.x == 0) d_stride = nonzero ? 1 : 2;
}

// ---------------- zero per-launch state ----------------
__global__ void zero_kernel() {
    int i = blockIdx.x * blockDim.x + threadIdx.x;
    if (i < NN) { d_degcnt[i] = 0; d_cursor[i] = 0; }
    if (i < GG * OUTD) d_sums[i] = 0.0f;
    if (i < GG) d_cnt[i] = 0.0f;
}

// ---------------- in-degree count ----------------
__global__ void count_kernel(const int* __restrict__ ei) {
    int e = blockIdx.x * blockDim.x + threadIdx.x;
    if (e < EE) {
        int st = d_stride;
        int dst = clampi(ei[(size_t)st * (EE + e)], 0, NN - 1);
        atomicAdd(&d_degcnt[dst], 1);
    }
}

// ---------------- scan stages ----------------
__global__ __launch_bounds__(256) void scanA_kernel() {
    int i = blockIdx.x * 256 + threadIdx.x;
    int v = (i < NN) ? d_degcnt[i] : 0;
    int lane = threadIdx.x & 31, wid = threadIdx.x >> 5;
    int s = v;
    #pragma unroll
    for (int o = 16; o > 0; o >>= 1) s += __shfl_down_sync(0xffffffffu, s, o);
    __shared__ int ws[8];
    if (lane == 0) ws[wid] = s;
    __syncthreads();
    if (threadIdx.x == 0) {
        int t = 0;
        #pragma unroll
        for (int w = 0; w < 8; w++) t += ws[w];
        d_blksum[blockIdx.x] = t;
    }
}

__global__ __launch_bounds__(256) void scanB_kernel() {
    __shared__ int s_a[256], s_b[256];
    int t = threadIdx.x;
    int v = (t < NB) ? d_blksum[t] : 0;
    s_a[t] = v;
    __syncthreads();
    int* cur = s_a; int* nxt = s_b;
    for (int off = 1; off < 256; off <<= 1) {
        int x = cur[t];
        if (t >= off) x += cur[t - off];
        nxt[t] = x;
        __syncthreads();
        int* tmp = cur; cur = nxt; nxt = tmp;
    }
    if (t < NB) d_blkoff[t] = cur[t] - v;
    if (t == 0) d_rowptr[NN] = EE;
}

__global__ __launch_bounds__(256) void scanC_kernel() {
    int i = blockIdx.x * 256 + threadIdx.x;
    int v = (i < NN) ? d_degcnt[i] : 0;
    int lane = threadIdx.x & 31, wid = threadIdx.x >> 5;
    int incl = v;
    #pragma unroll
    for (int o = 1; o < 32; o <<= 1) {
        int y = __shfl_up_sync(0xffffffffu, incl, o);
        if (lane >= o) incl += y;
    }
    __shared__ int ws[8];
    if (lane == 31) ws[wid] = incl;
    __syncthreads();
    int woff = 0;
    #pragma unroll
    for (int w = 0; w < 8; w++) woff += (w < wid) ? ws[w] : 0;
    if (i < NN) {
        d_rowptr[i] = d_blkoff[blockIdx.x] + woff + incl - v;
        d_dinv[i] = rsqrtf(1.0f + (float)v);
    }
}

// ---------------- scatter edges into CSR buckets ----------------
__global__ void scatter_kernel(const int* __restrict__ ei) {
    int e = blockIdx.x * blockDim.x + threadIdx.x;
    if (e < EE) {
        int st = d_stride;
        int dst = clampi(ei[(size_t)st * (EE + e)], 0, NN - 1);
        int src = clampi(ei[(size_t)st * e],        0, NN - 1);
        int pos = d_rowptr[dst] + atomicAdd(&d_cursor[dst], 1);
        if (pos >= 0 && pos < EE) d_esrc[pos] = src;
    }
}

// ---------------- TF32 tensor-core GEMM v3 -------------------------------------
// R9 structure, but: operands pre-converted to tf32 bits at staging, A fragments
// loaded via ldmatrix.m8n8.x4.b16 (1 LDSM replaces 8 LDS.32), zero cvt in loop.
__global__ __launch_bounds__(256) void gemm_tf32_kernel(
    const float* __restrict__ Aext, const float* __restrict__ B,
    const float* __restrict__ bias, int asel, int use_scale, int csel)
{
    __shared__ uint32_t As[64 * 132];   // tf32 bits, 33792 B (row stride 528B, 16B-mult)
    __shared__ uint32_t Bs[16 * 136];   // tf32 bits,  8704 B

    const float* A = (asel == 0) ? Aext : (asel == 1 ? d_h0 : d_h1);
    float* C = (csel == 0) ? d_g : (csel == 1 ? d_h0 : d_h1);

    int tid = threadIdx.x;
    int wid = tid >> 5, lane = tid & 31;
    int g = lane >> 2, t = lane & 3;
    int wm = wid & 1, wn = wid >> 1;        // warp grid 2 m x 4 n
    int row0 = blockIdx.x * 64;

    // stage A (convert once)
    {
        const float4* A4 = (const float4*)A;
        uint4* As4 = (uint4*)As;            // uint4 stride = 33
        #pragma unroll
        for (int i = 0; i < 8; i++) {
            int idx = i * 256 + tid;
            int r = idx >> 5, c = idx & 31;
            float4 v = (row0 + r < NN) ? A4[(size_t)(row0 + r) * 32 + c]
                                       : make_float4(0.f, 0.f, 0.f, 0.f);
            uint4 u;
            u.x = f2tf(v.x); u.y = f2tf(v.y); u.z = f2tf(v.z); u.w = f2tf(v.w);
            As4[r * 33 + c] = u;
        }
    }

    // per-lane ldmatrix base: lane L -> tile q = L>>3, row-in-tile rr = L&7
    // tile q: rows ar + ((q&1)<<3) + rr, col offset ((q>>1)<<2)  [+ kcol per atom]
    uint32_t a_base;
    {
        int q = lane >> 3, rr = lane & 7;
        int arow = wm * 32 + ((q & 1) << 3) + rr;
        uint32_t saddr = (uint32_t)__cvta_generic_to_shared(As);
        a_base = saddr + (uint32_t)(arow * 132 + ((q >> 1) << 2)) * 4u;
    }

    float acc[2][4][4];
    #pragma unroll
    for (int am = 0; am < 2; am++)
        #pragma unroll
        for (int an = 0; an < 4; an++)
            #pragma unroll
            for (int q = 0; q < 4; q++) acc[am][an][q] = 0.0f;

    const float4* B4 = (const float4*)B;

    for (int kc = 0; kc < 8; kc++) {
        __syncthreads();
        // stage B chunk rows [kc*16, kc*16+16) with cvt; uint4 stride = 34
        {
            uint4* Bs4 = (uint4*)Bs;
            #pragma unroll
            for (int i = 0; i < 2; i++) {
                int idx = i * 256 + tid;
                int r = idx >> 5, c = idx & 31;
                float4 v = B4[(size_t)(kc * 16 + r) * 32 + c];
                uint4 u;
                u.x = f2tf(v.x); u.y = f2tf(v.y); u.z = f2tf(v.z); u.w = f2tf(v.w);
                Bs4[r * 34 + c] = u;
            }
        }
        __syncthreads();

        #pragma unroll
        for (int ka = 0; ka < 2; ka++) {
            int kcol = kc * 16 + ka * 8;
            int kb = ka * 8;

            uint32_t a[2][4];
            #pragma unroll
            for (int am = 0; am < 2; am++) {
                uint32_t addr = a_base + (uint32_t)(am * 16 * 132 + kcol) * 4u;
                asm volatile(
                    "ldmatrix.sync.aligned.m8n8.x4.shared.b16 {%0,%1,%2,%3}, [%4];"
                    : "=r"(a[am][0]), "=r"(a[am][1]), "=r"(a[am][2]), "=r"(a[am][3])
                    : "r"(addr));
            }
            uint32_t b[4][2];
            #pragma unroll
            for (int an = 0; an < 4; an++) {
                int bc = wn * 32 + an * 8 + g;
                b[an][0] = Bs[(kb + t) * 136 + bc];
                b[an][1] = Bs[(kb + t + 4) * 136 + bc];
            }
            #pragma unroll
            for (int am = 0; am < 2; am++)
                #pragma unroll
                for (int an = 0; an < 4; an++) {
                    asm volatile(
                        "mma.sync.aligned.m16n8k8.row.col.f32.tf32.tf32.f32 "
                        "{%0,%1,%2,%3}, {%4,%5,%6,%7}, {%8,%9}, {%0,%1,%2,%3};"
                        : "+f"(acc[am][an][0]), "+f"(acc[am][an][1]),
                          "+f"(acc[am][an][2]), "+f"(acc[am][an][3])
                        : "r"(a[am][0]), "r"(a[am][1]), "r"(a[am][2]), "r"(a[am][3]),
                          "r"(b[an][0]), "r"(b[an][1]));
                }
        }
    }

    // epilogue: c0:(g,2t) c1:(g,2t+1) c2:(g+8,2t) c3:(g+8,2t+1)
    #pragma unroll
    for (int am = 0; am < 2; am++) {
        int r0a = row0 + wm * 32 + am * 16;
        int rA = r0a + g;
        int rB = r0a + g + 8;
        float sA = 1.0f, sB = 1.0f;
        if (use_scale) {
            if (rA < NN) sA = d_dinv[rA];
            if (rB < NN) sB = d_dinv[rB];
        }
        #pragma unroll
        for (int an = 0; an < 4; an++) {
            int col = wn * 32 + an * 8 + 2 * t;
            float bx = bias ? bias[col]     : 0.0f;
            float by = bias ? bias[col + 1] : 0.0f;
            if (rA < NN) {
                float2 o;
                o.x = (acc[am][an][0] + bx) * sA;
                o.y = (acc[am][an][1] + by) * sA;
                *(float2*)(C + (size_t)rA * HH + col) = o;
            }
            if (rB < NN) {
                float2 o;
                o.x = (acc[am][an][2] + bx) * sB;
                o.y = (acc[am][an][3] + by) * sB;
                *(float2*)(C + (size_t)rB * HH + col) = o;
            }
        }
    }
}

// ---------------- neighborhood aggregation (warp per node, MLP=4, fp32) --------
__global__ __launch_bounds__(256) void aggregate_kernel(
    const float* __restrict__ bias, int relu, int outsel)
{
    int node = blockIdx.x * 8 + (threadIdx.x >> 5);
    if (node >= NN) return;
    int lane = threadIdx.x & 31;
    float* out = (outsel == 1) ? d_h0 : d_h1;

    const float4* g4 = (const float4*)d_g;
    float4 acc = g4[(size_t)node * 32 + lane];   // self term

    int s = d_rowptr[node], e = d_rowptr[node + 1];
    int j = s;
    for (; j + 3 < e; j += 4) {
        int s0 = d_esrc[j], s1 = d_esrc[j + 1], s2 = d_esrc[j + 2], s3 = d_esrc[j + 3];
        float4 v0 = g4[(size_t)s0 * 32 + lane];
        float4 v1 = g4[(size_t)s1 * 32 + lane];
        float4 v2 = g4[(size_t)s2 * 32 + lane];
        float4 v3 = g4[(size_t)s3 * 32 + lane];
        acc.x += v0.x + v1.x + v2.x + v3.x;
        acc.y += v0.y + v1.y + v2.y + v3.y;
        acc.z += v0.z + v1.z + v2.z + v3.z;
        acc.w += v0.w + v1.w + v2.w + v3.w;
    }
    for (; j < e; j++) {
        int ss = d_esrc[j];
        float4 v = g4[(size_t)ss * 32 + lane];
        acc.x += v.x; acc.y += v.y; acc.z += v.z; acc.w += v.w;
    }

    float di = d_dinv[node];
    float4 b4 = ((const float4*)bias)[lane];
    float4 o;
    o.x = fmaf(acc.x, di, b4.x);
    o.y = fmaf(acc.y, di, b4.y);
    o.z = fmaf(acc.z, di, b4.z);
    o.w = fmaf(acc.w, di, b4.w);
    if (relu) {
        o.x = fmaxf(o.x, 0.f); o.y = fmaxf(o.y, 0.f);
        o.z = fmaxf(o.z, 0.f); o.w = fmaxf(o.w, 0.f);
    }
    ((float4*)out)[(size_t)node * 32 + lane] = o;
}

// ---------------- fused last-hop aggregation + classifier + pool ----------------
__global__ __launch_bounds__(256) void aggregate_cls_kernel(
    const float* __restrict__ bias, const int* __restrict__ batch,
    const float* __restrict__ Wc, const float* __restrict__ bc)
{
    __shared__ float sW[HH * OUTD];
    __shared__ float sB[OUTD];
    int tid = threadIdx.x;
    for (int i = tid; i < HH * OUTD; i += 256) sW[i] = Wc[i];
    if (tid < OUTD) sB[tid] = bc[tid];
    __syncthreads();

    int node = blockIdx.x * 8 + (tid >> 5);
    if (node >= NN) return;
    int lane = tid & 31;

    const float4* g4 = (const float4*)d_g;
    float4 acc = g4[(size_t)node * 32 + lane];

    int s = d_rowptr[node], e = d_rowptr[node + 1];
    int j = s;
    for (; j + 3 < e; j += 4) {
        int s0 = d_esrc[j], s1 = d_esrc[j + 1], s2 = d_esrc[j + 2], s3 = d_esrc[j + 3];
        float4 v0 = g4[(size_t)s0 * 32 + lane];
        float4 v1 = g4[(size_t)s1 * 32 + lane];
        float4 v2 = g4[(size_t)s2 * 32 + lane];
        float4 v3 = g4[(size_t)s3 * 32 + lane];
        acc.x += v0.x + v1.x + v2.x + v3.x;
        acc.y += v0.y + v1.y + v2.y + v3.y;
        acc.z += v0.z + v1.z + v2.z + v3.z;
        acc.w += v0.w + v1.w + v2.w + v3.w;
    }
    for (; j < e; j++) {
        int ss = d_esrc[j];
        float4 v = g4[(size_t)ss * 32 + lane];
        acc.x += v.x; acc.y += v.y; acc.z += v.z; acc.w += v.w;
    }

    float di = d_dinv[node];
    float4 b4 = ((const float4*)bias)[lane];
    float4 o;                      // cols 4*lane .. 4*lane+3 (no relu on last hop)
    o.x = fmaf(acc.x, di, b4.x);
    o.y = fmaf(acc.y, di, b4.y);
    o.z = fmaf(acc.z, di, b4.z);
    o.w = fmaf(acc.w, di, b4.w);

    int c0 = 4 * lane;
    float p[OUTD];
    #pragma unroll
    for (int d = 0; d < OUTD; d++) {
        float v = o.x * sW[(c0 + 0) * OUTD + d];
        v = fmaf(o.y, sW[(c0 + 1) * OUTD + d], v);
        v = fmaf(o.z, sW[(c0 + 2) * OUTD + d], v);
        v = fmaf(o.w, sW[(c0 + 3) * OUTD + d], v);
        p[d] = v;
    }
    #pragma unroll
    for (int off = 16; off > 0; off >>= 1) {
        #pragma unroll
        for (int d = 0; d < OUTD; d++)
            p[d] += __shfl_xor_sync(0xffffffffu, p[d], off);
    }
    int st = d_stride;
    int b = clampi(batch[(size_t)st * node], 0, GG - 1);
    if (lane < OUTD) {
        float v = p[0];
        #pragma unroll
        for (int d = 1; d < OUTD; d++) v = (lane == d) ? p[d] : v;
        atomicAdd(&d_sums[b * OUTD + lane], v + sB[lane]);
    }
    if (lane == OUTD) atomicAdd(&d_cnt[b], 1.0f);
}

// ---------------- final divide ----------------
__global__ void finalize_kernel(float* __restrict__ out) {
    int i = blockIdx.x * blockDim.x + threadIdx.x;
    if (i < GG * OUTD) {
        float c = d_cnt[i / OUTD];
        out[i] = d_sums[i] / fmaxf(c, 1.0f);
    }
}

// ---------------- launch ----------------
extern "C" void kernel_launch(void* const* d_in, const int* in_sizes, int n_in,
                              void* d_out, int out_size) {
    const float* x      = (const float*)d_in[0];
    const int*   ei     = (const int*)d_in[1];
    const int*   batch  = (const int*)d_in[2];
    const float* W_in   = (const float*)d_in[3];
    const float* b_in   = (const float*)d_in[4];
    const float* W_hops = (const float*)d_in[5];
    const float* b_hops = (const float*)d_in[6];
    const float* W_cls  = (const float*)d_in[7];
    const float* b_cls  = (const float*)d_in[8];
    float* out = (float*)d_out;

    const int GB = (NN + 63) / 64;

    detect_kernel<<<1, 128>>>(ei);
    zero_kernel<<<(NN + 255) / 256, 256>>>();
    count_kernel<<<(EE + 255) / 256, 256>>>(ei);
    // encoder GEMM in slot 4 for stable ncu sampling
    gemm_tf32_kernel<<<GB, 256>>>(x, W_in, b_in, 0, 0, 1);
    scanA_kernel<<<NB, 256>>>();
    scanB_kernel<<<1, 256>>>();
    scanC_kernel<<<NB, 256>>>();
    scatter_kernel<<<(EE + 255) / 256, 256>>>(ei);

    int cur = 1;   // d_h0
    for (int hop = 0; hop < NHOPS; hop++) {
        int nxt = (cur == 1) ? 2 : 1;
        gemm_tf32_kernel<<<GB, 256>>>(nullptr, W_hops + (size_t)hop * HH * HH,
                                      nullptr, cur, 1, 0);
        if (hop < NHOPS - 1) {
            aggregate_kernel<<<(NN + 7) / 8, 256>>>(b_hops + hop * HH, 1, nxt);
        } else {
            aggregate_cls_kernel<<<(NN + 7) / 8, 256>>>(b_hops + hop * HH,
                                                        batch, W_cls, b_cls);
        }
        cur = nxt;
    }

    finalize_kernel<<<(GG * OUTD + 255) / 256, 256>>>(out);
}

// round 13
// speedup vs baseline: 1.5067x; 1.0831x over previous
#include <cuda_runtime.h>
#include <cuda_fp16.h>
#include <cstdint>

#define NN    50000
#define EE    800000
#define HH    128
#define GG    128
#define OUTD  10
#define NHOPS 4
#define NB    ((NN + 255) / 256)   // 196 scan blocks

// ---------------- device scratch (static, no runtime allocation) ----------------
__device__ __align__(16) float d_h0[NN * HH];
__device__ __align__(16) float d_h1[NN * HH];
__device__ __align__(16) float d_g[NN * HH];
__device__ float d_dinv[NN];
__device__ int   d_degcnt[NN];
__device__ int   d_rowptr[NN + 1];
__device__ int   d_cursor[NN];
__device__ int   d_esrc[EE];
__device__ float d_sums[GG * OUTD];
__device__ float d_cnt[GG];
__device__ int   d_stride;     // 1 = int32 inputs, 2 = int64 inputs
__device__ int   d_blksum[NB];
__device__ int   d_blkoff[NB];

__device__ __forceinline__ int clampi(int v, int lo, int hi) {
    return v < lo ? lo : (v > hi ? hi : v);
}

__device__ __forceinline__ uint32_t packh2(float a, float b) {
    __half2 h = __floats2half2_rn(a, b);
    return *(uint32_t*)&h;
}

// ---------------- dtype detection: int32 vs int64 edge_index -------------------
__global__ void detect_kernel(const int* __restrict__ ei_words) {
    __shared__ int nonzero;
    if (threadIdx.x == 0) nonzero = 0;
    __syncthreads();
    int w = ei_words[2 * threadIdx.x + 1];
    if (w != 0) atomicOr(&nonzero, 1);
    __syncthreads();
    if (threadIdx.x == 0) d_stride = nonzero ? 1 : 2;
}

// ---------------- zero per-launch state ----------------
__global__ void zero_kernel() {
    int i = blockIdx.x * blockDim.x + threadIdx.x;
    if (i < NN) { d_degcnt[i] = 0; d_cursor[i] = 0; }
    if (i < GG * OUTD) d_sums[i] = 0.0f;
    if (i < GG) d_cnt[i] = 0.0f;
}

// ---------------- in-degree count ----------------
__global__ void count_kernel(const int* __restrict__ ei) {
    int e = blockIdx.x * blockDim.x + threadIdx.x;
    if (e < EE) {
        int st = d_stride;
        int dst = clampi(ei[(size_t)st * (EE + e)], 0, NN - 1);
        atomicAdd(&d_degcnt[dst], 1);
    }
}

// ---------------- scan stages ----------------
__global__ __launch_bounds__(256) void scanA_kernel() {
    int i = blockIdx.x * 256 + threadIdx.x;
    int v = (i < NN) ? d_degcnt[i] : 0;
    int lane = threadIdx.x & 31, wid = threadIdx.x >> 5;
    int s = v;
    #pragma unroll
    for (int o = 16; o > 0; o >>= 1) s += __shfl_down_sync(0xffffffffu, s, o);
    __shared__ int ws[8];
    if (lane == 0) ws[wid] = s;
    __syncthreads();
    if (threadIdx.x == 0) {
        int t = 0;
        #pragma unroll
        for (int w = 0; w < 8; w++) t += ws[w];
        d_blksum[blockIdx.x] = t;
    }
}

__global__ __launch_bounds__(256) void scanB_kernel() {
    __shared__ int s_a[256], s_b[256];
    int t = threadIdx.x;
    int v = (t < NB) ? d_blksum[t] : 0;
    s_a[t] = v;
    __syncthreads();
    int* cur = s_a; int* nxt = s_b;
    for (int off = 1; off < 256; off <<= 1) {
        int x = cur[t];
        if (t >= off) x += cur[t - off];
        nxt[t] = x;
        __syncthreads();
        int* tmp = cur; cur = nxt; nxt = tmp;
    }
    if (t < NB) d_blkoff[t] = cur[t] - v;
    if (t == 0) d_rowptr[NN] = EE;
}

__global__ __launch_bounds__(256) void scanC_kernel() {
    int i = blockIdx.x * 256 + threadIdx.x;
    int v = (i < NN) ? d_degcnt[i] : 0;
    int lane = threadIdx.x & 31, wid = threadIdx.x >> 5;
    int incl = v;
    #pragma unroll
    for (int o = 1; o < 32; o <<= 1) {
        int y = __shfl_up_sync(0xffffffffu, incl, o);
        if (lane >= o) incl += y;
    }
    __shared__ int ws[8];
    if (lane == 31) ws[wid] = incl;
    __syncthreads();
    int woff = 0;
    #pragma unroll
    for (int w = 0; w < 8; w++) woff += (w < wid) ? ws[w] : 0;
    if (i < NN) {
        d_rowptr[i] = d_blkoff[blockIdx.x] + woff + incl - v;
        d_dinv[i] = rsqrtf(1.0f + (float)v);
    }
}

// ---------------- scatter edges into CSR buckets ----------------
__global__ void scatter_kernel(const int* __restrict__ ei) {
    int e = blockIdx.x * blockDim.x + threadIdx.x;
    if (e < EE) {
        int st = d_stride;
        int dst = clampi(ei[(size_t)st * (EE + e)], 0, NN - 1);
        int src = clampi(ei[(size_t)st * e],        0, NN - 1);
        int pos = d_rowptr[dst] + atomicAdd(&d_cursor[dst], 1);
        if (pos >= 0 && pos < EE) d_esrc[pos] = src;
    }
}

// ---------------- FP16 tensor-core GEMM v4 -------------------------------------
// Whole B (128x128 fp16 = 32KB) + A tile (64x128 fp16 = 16KB) in 48KB smem.
// Single staging phase + one sync; mainloop = pure LDSM + HMMA (K=16/step).
// XOR swizzle on 16B units: unit' = u ^ (row & 7), conflict-free for STS & LDSM.
__global__ __launch_bounds__(256) void gemm_f16_kernel(
    const float* __restrict__ Aext, const float* __restrict__ B,
    const float* __restrict__ bias, int asel, int use_scale, int csel)
{
    __shared__ uint4 As16[64 * 16];    // 16 KB (row = 16 units of 16B = 8 halves)
    __shared__ uint4 Bs16[128 * 16];   // 32 KB

    const float* A = (asel == 0) ? Aext : (asel == 1 ? d_h0 : d_h1);
    float* C = (csel == 0) ? d_g : (csel == 1 ? d_h0 : d_h1);

    int tid = threadIdx.x;
    int wid = tid >> 5, lane = tid & 31;
    int g = lane >> 2, t = lane & 3;
    int wm = wid & 1, wn = wid >> 1;        // warp grid 2 m x 4 n
    int row0 = blockIdx.x * 64;

    const float4* A4 = (const float4*)A;
    const float4* B4 = (const float4*)B;

    // stage A: 1024 units, 4 per thread
    #pragma unroll
    for (int i = 0; i < 4; i++) {
        int idx = i * 256 + tid;
        int r = idx >> 4, u = idx & 15;
        float4 v0 = make_float4(0.f, 0.f, 0.f, 0.f), v1 = v0;
        if (row0 + r < NN) {
            v0 = A4[(size_t)(row0 + r) * 32 + u * 2];
            v1 = A4[(size_t)(row0 + r) * 32 + u * 2 + 1];
        }
        uint4 h;
        h.x = packh2(v0.x, v0.y); h.y = packh2(v0.z, v0.w);
        h.z = packh2(v1.x, v1.y); h.w = packh2(v1.z, v1.w);
        As16[r * 16 + (u ^ (r & 7))] = h;
    }
    // stage B: 2048 units, 8 per thread
    #pragma unroll
    for (int i = 0; i < 8; i++) {
        int idx = i * 256 + tid;
        int r = idx >> 4, u = idx & 15;
        float4 v0 = B4[(size_t)r * 32 + u * 2];
        float4 v1 = B4[(size_t)r * 32 + u * 2 + 1];
        uint4 h;
        h.x = packh2(v0.x, v0.y); h.y = packh2(v0.z, v0.w);
        h.z = packh2(v1.x, v1.y); h.w = packh2(v1.z, v1.w);
        Bs16[r * 16 + (u ^ (r & 7))] = h;
    }
    __syncthreads();

    // lane decode for ldmatrix
    int cg = lane >> 4;        // column group (0/1)
    int l7 = lane & 7;
    int l15 = lane & 15;

    uint32_t Abase = (uint32_t)__cvta_generic_to_shared(As16);
    uint32_t Bbase = (uint32_t)__cvta_generic_to_shared(Bs16);
    // A row byte base per am (row stride 256B); row&7 == l7 for all am
    uint32_t arow[2];
    #pragma unroll
    for (int am = 0; am < 2; am++)
        arow[am] = Abase + (uint32_t)(wm * 32 + am * 16 + l15) * 256u;
    // B base per n16-group (rows advance 16/step = 4096B/step; row&7 == l7)
    uint32_t bbase[2];
    #pragma unroll
    for (int an16 = 0; an16 < 2; an16++) {
        uint32_t up = (uint32_t)((wn * 4 + an16 * 2 + cg) ^ l7);
        bbase[an16] = Bbase + (uint32_t)l15 * 256u + up * 16u;
    }

    float acc[2][4][4];
    #pragma unroll
    for (int am = 0; am < 2; am++)
        #pragma unroll
        for (int an = 0; an < 4; an++)
            #pragma unroll
            for (int q = 0; q < 4; q++) acc[am][an][q] = 0.0f;

    #pragma unroll
    for (int kc = 0; kc < 8; kc++) {
        uint32_t ua = (uint32_t)(((kc * 2 + cg) ^ l7) * 16);

        uint32_t a[2][4];
        #pragma unroll
        for (int am = 0; am < 2; am++) {
            asm volatile(
                "ldmatrix.sync.aligned.m8n8.x4.shared.b16 {%0,%1,%2,%3}, [%4];"
                : "=r"(a[am][0]), "=r"(a[am][1]), "=r"(a[am][2]), "=r"(a[am][3])
                : "r"(arow[am] + ua));
        }
        uint32_t br[2][4];
        #pragma unroll
        for (int an16 = 0; an16 < 2; an16++) {
            asm volatile(
                "ldmatrix.sync.aligned.m8n8.x4.trans.shared.b16 {%0,%1,%2,%3}, [%4];"
                : "=r"(br[an16][0]), "=r"(br[an16][1]), "=r"(br[an16][2]), "=r"(br[an16][3])
                : "r"(bbase[an16] + (uint32_t)kc * 4096u));
        }
        #pragma unroll
        for (int am = 0; am < 2; am++)
            #pragma unroll
            for (int an = 0; an < 4; an++) {
                int an16 = an >> 1, hf = an & 1;
                asm volatile(
                    "mma.sync.aligned.m16n8k16.row.col.f32.f16.f16.f32 "
                    "{%0,%1,%2,%3}, {%4,%5,%6,%7}, {%8,%9}, {%0,%1,%2,%3};"
                    : "+f"(acc[am][an][0]), "+f"(acc[am][an][1]),
                      "+f"(acc[am][an][2]), "+f"(acc[am][an][3])
                    : "r"(a[am][0]), "r"(a[am][1]), "r"(a[am][2]), "r"(a[am][3]),
                      "r"(br[an16][hf * 2]), "r"(br[an16][hf * 2 + 1]));
            }
    }

    // epilogue: c0:(g,2t) c1:(g,2t+1) c2:(g+8,2t) c3:(g+8,2t+1)
    #pragma unroll
    for (int am = 0; am < 2; am++) {
        int r0a = row0 + wm * 32 + am * 16;
        int rA = r0a + g;
        int rB = r0a + g + 8;
        float sA = 1.0f, sB = 1.0f;
        if (use_scale) {
            if (rA < NN) sA = d_dinv[rA];
            if (rB < NN) sB = d_dinv[rB];
        }
        #pragma unroll
        for (int an = 0; an < 4; an++) {
            int col = wn * 32 + an * 8 + 2 * t;
            float bx = bias ? bias[col]     : 0.0f;
            float by = bias ? bias[col + 1] : 0.0f;
            if (rA < NN) {
                float2 o;
                o.x = (acc[am][an][0] + bx) * sA;
                o.y = (acc[am][an][1] + by) * sA;
                *(float2*)(C + (size_t)rA * HH + col) = o;
            }
            if (rB < NN) {
                float2 o;
                o.x = (acc[am][an][2] + bx) * sB;
                o.y = (acc[am][an][3] + by) * sB;
                *(float2*)(C + (size_t)rB * HH + col) = o;
            }
        }
    }
}

// ---------------- neighborhood aggregation (warp per node, MLP=4, fp32) --------
__global__ __launch_bounds__(256) void aggregate_kernel(
    const float* __restrict__ bias, int relu, int outsel)
{
    int node = blockIdx.x * 8 + (threadIdx.x >> 5);
    if (node >= NN) return;
    int lane = threadIdx.x & 31;
    float* out = (outsel == 1) ? d_h0 : d_h1;

    const float4* g4 = (const float4*)d_g;
    float4 acc = g4[(size_t)node * 32 + lane];   // self term

    int s = d_rowptr[node], e = d_rowptr[node + 1];
    int j = s;
    for (; j + 3 < e; j += 4) {
        int s0 = d_esrc[j], s1 = d_esrc[j + 1], s2 = d_esrc[j + 2], s3 = d_esrc[j + 3];
        float4 v0 = g4[(size_t)s0 * 32 + lane];
        float4 v1 = g4[(size_t)s1 * 32 + lane];
        float4 v2 = g4[(size_t)s2 * 32 + lane];
        float4 v3 = g4[(size_t)s3 * 32 + lane];
        acc.x += v0.x + v1.x + v2.x + v3.x;
        acc.y += v0.y + v1.y + v2.y + v3.y;
        acc.z += v0.z + v1.z + v2.z + v3.z;
        acc.w += v0.w + v1.w + v2.w + v3.w;
    }
    for (; j < e; j++) {
        int ss = d_esrc[j];
        float4 v = g4[(size_t)ss * 32 + lane];
        acc.x += v.x; acc.y += v.y; acc.z += v.z; acc.w += v.w;
    }

    float di = d_dinv[node];
    float4 b4 = ((const float4*)bias)[lane];
    float4 o;
    o.x = fmaf(acc.x, di, b4.x);
    o.y = fmaf(acc.y, di, b4.y);
    o.z = fmaf(acc.z, di, b4.z);
    o.w = fmaf(acc.w, di, b4.w);
    if (relu) {
        o.x = fmaxf(o.x, 0.f); o.y = fmaxf(o.y, 0.f);
        o.z = fmaxf(o.z, 0.f); o.w = fmaxf(o.w, 0.f);
    }
    ((float4*)out)[(size_t)node * 32 + lane] = o;
}

// ---------------- fused last-hop aggregation + classifier + pool ----------------
__global__ __launch_bounds__(256) void aggregate_cls_kernel(
    const float* __restrict__ bias, const int* __restrict__ batch,
    const float* __restrict__ Wc, const float* __restrict__ bc)
{
    __shared__ float sW[HH * OUTD];
    __shared__ float sB[OUTD];
    int tid = threadIdx.x;
    for (int i = tid; i < HH * OUTD; i += 256) sW[i] = Wc[i];
    if (tid < OUTD) sB[tid] = bc[tid];
    __syncthreads();

    int node = blockIdx.x * 8 + (tid >> 5);
    if (node >= NN) return;
    int lane = tid & 31;

    const float4* g4 = (const float4*)d_g;
    float4 acc = g4[(size_t)node * 32 + lane];

    int s = d_rowptr[node], e = d_rowptr[node + 1];
    int j = s;
    for (; j + 3 < e; j += 4) {
        int s0 = d_esrc[j], s1 = d_esrc[j + 1], s2 = d_esrc[j + 2], s3 = d_esrc[j + 3];
        float4 v0 = g4[(size_t)s0 * 32 + lane];
        float4 v1 = g4[(size_t)s1 * 32 + lane];
        float4 v2 = g4[(size_t)s2 * 32 + lane];
        float4 v3 = g4[(size_t)s3 * 32 + lane];
        acc.x += v0.x + v1.x + v2.x + v3.x;
        acc.y += v0.y + v1.y + v2.y + v3.y;
        acc.z += v0.z + v1.z + v2.z + v3.z;
        acc.w += v0.w + v1.w + v2.w + v3.w;
    }
    for (; j < e; j++) {
        int ss = d_esrc[j];
        float4 v = g4[(size_t)ss * 32 + lane];
        acc.x += v.x; acc.y += v.y; acc.z += v.z; acc.w += v.w;
    }

    float di = d_dinv[node];
    float4 b4 = ((const float4*)bias)[lane];
    float4 o;                      // cols 4*lane .. 4*lane+3 (no relu on last hop)
    o.x = fmaf(acc.x, di, b4.x);
    o.y = fmaf(acc.y, di, b4.y);
    o.z = fmaf(acc.z, di, b4.z);
    o.w = fmaf(acc.w, di, b4.w);

    int c0 = 4 * lane;
    float p[OUTD];
    #pragma unroll
    for (int d = 0; d < OUTD; d++) {
        float v = o.x * sW[(c0 + 0) * OUTD + d];
        v = fmaf(o.y, sW[(c0 + 1) * OUTD + d], v);
        v = fmaf(o.z, sW[(c0 + 2) * OUTD + d], v);
        v = fmaf(o.w, sW[(c0 + 3) * OUTD + d], v);
        p[d] = v;
    }
    #pragma unroll
    for (int off = 16; off > 0; off >>= 1) {
        #pragma unroll
        for (int d = 0; d < OUTD; d++)
            p[d] += __shfl_xor_sync(0xffffffffu, p[d], off);
    }
    int st = d_stride;
    int b = clampi(batch[(size_t)st * node], 0, GG - 1);
    if (lane < OUTD) {
        float v = p[0];
        #pragma unroll
        for (int d = 1; d < OUTD; d++) v = (lane == d) ? p[d] : v;
        atomicAdd(&d_sums[b * OUTD + lane], v + sB[lane]);
    }
    if (lane == OUTD) atomicAdd(&d_cnt[b], 1.0f);
}

// ---------------- final divide ----------------
__global__ void finalize_kernel(float* __restrict__ out) {
    int i = blockIdx.x * blockDim.x + threadIdx.x;
    if (i < GG * OUTD) {
        float c = d_cnt[i / OUTD];
        out[i] = d_sums[i] / fmaxf(c, 1.0f);
    }
}

// ---------------- launch ----------------
extern "C" void kernel_launch(void* const* d_in, const int* in_sizes, int n_in,
                              void* d_out, int out_size) {
    const float* x      = (const float*)d_in[0];
    const int*   ei     = (const int*)d_in[1];
    const int*   batch  = (const int*)d_in[2];
    const float* W_in   = (const float*)d_in[3];
    const float* b_in   = (const float*)d_in[4];
    const float* W_hops = (const float*)d_in[5];
    const float* b_hops = (const float*)d_in[6];
    const float* W_cls  = (const float*)d_in[7];
    const float* b_cls  = (const float*)d_in[8];
    float* out = (float*)d_out;

    const int GB = (NN + 63) / 64;

    detect_kernel<<<1, 128>>>(ei);
    zero_kernel<<<(NN + 255) / 256, 256>>>();
    count_kernel<<<(EE + 255) / 256, 256>>>(ei);
    // encoder GEMM in slot 4 for stable ncu sampling
    gemm_f16_kernel<<<GB, 256>>>(x, W_in, b_in, 0, 0, 1);
    scanA_kernel<<<NB, 256>>>();
    scanB_kernel<<<1, 256>>>();
    scanC_kernel<<<NB, 256>>>();
    scatter_kernel<<<(EE + 255) / 256, 256>>>(ei);

    int cur = 1;   // d_h0
    for (int hop = 0; hop < NHOPS; hop++) {
        int nxt = (cur == 1) ? 2 : 1;
        gemm_f16_kernel<<<GB, 256>>>(nullptr, W_hops + (size_t)hop * HH * HH,
                                     nullptr, cur, 1, 0);
        if (hop < NHOPS - 1) {
            aggregate_kernel<<<(NN + 7) / 8, 256>>>(b_hops + hop * HH, 1, nxt);
        } else {
            aggregate_cls_kernel<<<(NN + 7) / 8, 256>>>(b_hops + hop * HH,
                                                        batch, W_cls, b_cls);
        }
        cur = nxt;
    }

    finalize_kernel<<<(GG * OUTD + 255) / 256, 256>>>(out);
}

// round 14
// speedup vs baseline: 1.5840x; 1.0513x over previous
#include <cuda_runtime.h>
#include <cuda_fp16.h>
#include <cstdint>

#define NN    50000
#define EE    800000
#define HH    128
#define GG    128
#define OUTD  10
#define NHOPS 4
#define NB    ((NN + 255) / 256)   // 196 scan blocks

// ---------------- device scratch (static, no runtime allocation) ----------------
__device__ __align__(16) float d_h0[NN * HH];
__device__ __align__(16) float d_h1[NN * HH];
__device__ __align__(16) float d_g[NN * HH];
__device__ float d_dinv[NN];
__device__ int   d_degcnt[NN];
__device__ int   d_rowptr[NN + 1];
__device__ int   d_cursor[NN];
__device__ int   d_esrc[EE];
__device__ float d_sums[GG * OUTD];
__device__ float d_cnt[GG];
__device__ int   d_stride;     // 1 = int32 inputs, 2 = int64 inputs
__device__ int   d_blksum[NB];
__device__ int   d_blkoff[NB];

__device__ __forceinline__ int clampi(int v, int lo, int hi) {
    return v < lo ? lo : (v > hi ? hi : v);
}

__device__ __forceinline__ uint32_t packh2(float a, float b) {
    __half2 h = __floats2half2_rn(a, b);
    return *(uint32_t*)&h;
}

// ---------------- dtype detection: int32 vs int64 edge_index -------------------
__global__ void detect_kernel(const int* __restrict__ ei_words) {
    __shared__ int nonzero;
    if (threadIdx.x == 0) nonzero = 0;
    __syncthreads();
    int w = ei_words[2 * threadIdx.x + 1];
    if (w != 0) atomicOr(&nonzero, 1);
    __syncthreads();
    if (threadIdx.x == 0) d_stride = nonzero ? 1 : 2;
}

// ---------------- zero per-launch state ----------------
__global__ void zero_kernel() {
    int i = blockIdx.x * blockDim.x + threadIdx.x;
    if (i < NN) { d_degcnt[i] = 0; d_cursor[i] = 0; }
    if (i < GG * OUTD) d_sums[i] = 0.0f;
    if (i < GG) d_cnt[i] = 0.0f;
}

// ---------------- in-degree count ----------------
__global__ void count_kernel(const int* __restrict__ ei) {
    int e = blockIdx.x * blockDim.x + threadIdx.x;
    if (e < EE) {
        int st = d_stride;
        int dst = clampi(ei[(size_t)st * (EE + e)], 0, NN - 1);
        atomicAdd(&d_degcnt[dst], 1);
    }
}

// ---------------- scan stages ----------------
__global__ __launch_bounds__(256) void scanA_kernel() {
    int i = blockIdx.x * 256 + threadIdx.x;
    int v = (i < NN) ? d_degcnt[i] : 0;
    int lane = threadIdx.x & 31, wid = threadIdx.x >> 5;
    int s = v;
    #pragma unroll
    for (int o = 16; o > 0; o >>= 1) s += __shfl_down_sync(0xffffffffu, s, o);
    __shared__ int ws[8];
    if (lane == 0) ws[wid] = s;
    __syncthreads();
    if (threadIdx.x == 0) {
        int t = 0;
        #pragma unroll
        for (int w = 0; w < 8; w++) t += ws[w];
        d_blksum[blockIdx.x] = t;
    }
}

__global__ __launch_bounds__(256) void scanB_kernel() {
    __shared__ int s_a[256], s_b[256];
    int t = threadIdx.x;
    int v = (t < NB) ? d_blksum[t] : 0;
    s_a[t] = v;
    __syncthreads();
    int* cur = s_a; int* nxt = s_b;
    for (int off = 1; off < 256; off <<= 1) {
        int x = cur[t];
        if (t >= off) x += cur[t - off];
        nxt[t] = x;
        __syncthreads();
        int* tmp = cur; cur = nxt; nxt = tmp;
    }
    if (t < NB) d_blkoff[t] = cur[t] - v;
    if (t == 0) d_rowptr[NN] = EE;
}

__global__ __launch_bounds__(256) void scanC_kernel() {
    int i = blockIdx.x * 256 + threadIdx.x;
    int v = (i < NN) ? d_degcnt[i] : 0;
    int lane = threadIdx.x & 31, wid = threadIdx.x >> 5;
    int incl = v;
    #pragma unroll
    for (int o = 1; o < 32; o <<= 1) {
        int y = __shfl_up_sync(0xffffffffu, incl, o);
        if (lane >= o) incl += y;
    }
    __shared__ int ws[8];
    if (lane == 31) ws[wid] = incl;
    __syncthreads();
    int woff = 0;
    #pragma unroll
    for (int w = 0; w < 8; w++) woff += (w < wid) ? ws[w] : 0;
    if (i < NN) {
        d_rowptr[i] = d_blkoff[blockIdx.x] + woff + incl - v;
        d_dinv[i] = rsqrtf(1.0f + (float)v);
    }
}

// ---------------- scatter edges into CSR buckets ----------------
__global__ void scatter_kernel(const int* __restrict__ ei) {
    int e = blockIdx.x * blockDim.x + threadIdx.x;
    if (e < EE) {
        int st = d_stride;
        int dst = clampi(ei[(size_t)st * (EE + e)], 0, NN - 1);
        int src = clampi(ei[(size_t)st * e],        0, NN - 1);
        int pos = d_rowptr[dst] + atomicAdd(&d_cursor[dst], 1);
        if (pos >= 0 && pos < EE) d_esrc[pos] = src;
    }
}

// ---------------- FP16 tensor-core GEMM v5 -------------------------------------
// B (128x128 fp16 = 32KB) staged ONCE per block; block loops over 2 A tiles of
// 64 rows (16KB each). Mainloop = pure LDSM + HMMA (K=16/step). XOR swizzle.
__global__ __launch_bounds__(256) void gemm_f16_kernel(
    const float* __restrict__ Aext, const float* __restrict__ B,
    const float* __restrict__ bias, int asel, int use_scale, int csel)
{
    __shared__ uint4 As16[64 * 16];    // 16 KB (row = 16 units of 16B = 8 halves)
    __shared__ uint4 Bs16[128 * 16];   // 32 KB

    const float* A = (asel == 0) ? Aext : (asel == 1 ? d_h0 : d_h1);
    float* C = (csel == 0) ? d_g : (csel == 1 ? d_h0 : d_h1);

    int tid = threadIdx.x;
    int wid = tid >> 5, lane = tid & 31;
    int g = lane >> 2, t = lane & 3;
    int wm = wid & 1, wn = wid >> 1;        // warp grid 2 m x 4 n
    const float4* A4 = (const float4*)A;
    const float4* B4 = (const float4*)B;

    // stage B once: 2048 units, 8 per thread
    #pragma unroll
    for (int i = 0; i < 8; i++) {
        int idx = i * 256 + tid;
        int r = idx >> 4, u = idx & 15;
        float4 v0 = B4[(size_t)r * 32 + u * 2];
        float4 v1 = B4[(size_t)r * 32 + u * 2 + 1];
        uint4 h;
        h.x = packh2(v0.x, v0.y); h.y = packh2(v0.z, v0.w);
        h.z = packh2(v1.x, v1.y); h.w = packh2(v1.z, v1.w);
        Bs16[r * 16 + (u ^ (r & 7))] = h;
    }

    // lane decode for ldmatrix (loop-invariant)
    int cg = lane >> 4;        // column group (0/1)
    int l7 = lane & 7;
    int l15 = lane & 15;
    uint32_t Abase = (uint32_t)__cvta_generic_to_shared(As16);
    uint32_t Bbase = (uint32_t)__cvta_generic_to_shared(Bs16);
    uint32_t arow[2];
    #pragma unroll
    for (int am = 0; am < 2; am++)
        arow[am] = Abase + (uint32_t)(wm * 32 + am * 16 + l15) * 256u;
    uint32_t bbase[2];
    #pragma unroll
    for (int an16 = 0; an16 < 2; an16++) {
        uint32_t up = (uint32_t)((wn * 4 + an16 * 2 + cg) ^ l7);
        bbase[an16] = Bbase + (uint32_t)l15 * 256u + up * 16u;
    }

    #pragma unroll
    for (int sTile = 0; sTile < 2; sTile++) {
        int row0 = (blockIdx.x * 2 + sTile) * 64;

        // stage A tile: 1024 units, 4 per thread
        #pragma unroll
        for (int i = 0; i < 4; i++) {
            int idx = i * 256 + tid;
            int r = idx >> 4, u = idx & 15;
            float4 v0 = make_float4(0.f, 0.f, 0.f, 0.f), v1 = v0;
            if (row0 + r < NN) {
                v0 = A4[(size_t)(row0 + r) * 32 + u * 2];
                v1 = A4[(size_t)(row0 + r) * 32 + u * 2 + 1];
            }
            uint4 h;
            h.x = packh2(v0.x, v0.y); h.y = packh2(v0.z, v0.w);
            h.z = packh2(v1.x, v1.y); h.w = packh2(v1.z, v1.w);
            As16[r * 16 + (u ^ (r & 7))] = h;
        }
        __syncthreads();

        float acc[2][4][4];
        #pragma unroll
        for (int am = 0; am < 2; am++)
            #pragma unroll
            for (int an = 0; an < 4; an++)
                #pragma unroll
                for (int q = 0; q < 4; q++) acc[am][an][q] = 0.0f;

        #pragma unroll
        for (int kc = 0; kc < 8; kc++) {
            uint32_t ua = (uint32_t)(((kc * 2 + cg) ^ l7) * 16);

            uint32_t a[2][4];
            #pragma unroll
            for (int am = 0; am < 2; am++) {
                asm volatile(
                    "ldmatrix.sync.aligned.m8n8.x4.shared.b16 {%0,%1,%2,%3}, [%4];"
                    : "=r"(a[am][0]), "=r"(a[am][1]), "=r"(a[am][2]), "=r"(a[am][3])
                    : "r"(arow[am] + ua));
            }
            uint32_t br[2][4];
            #pragma unroll
            for (int an16 = 0; an16 < 2; an16++) {
                asm volatile(
                    "ldmatrix.sync.aligned.m8n8.x4.trans.shared.b16 {%0,%1,%2,%3}, [%4];"
                    : "=r"(br[an16][0]), "=r"(br[an16][1]), "=r"(br[an16][2]), "=r"(br[an16][3])
                    : "r"(bbase[an16] + (uint32_t)kc * 4096u));
            }
            #pragma unroll
            for (int am = 0; am < 2; am++)
                #pragma unroll
                for (int an = 0; an < 4; an++) {
                    int an16 = an >> 1, hf = an & 1;
                    asm volatile(
                        "mma.sync.aligned.m16n8k16.row.col.f32.f16.f16.f32 "
                        "{%0,%1,%2,%3}, {%4,%5,%6,%7}, {%8,%9}, {%0,%1,%2,%3};"
                        : "+f"(acc[am][an][0]), "+f"(acc[am][an][1]),
                          "+f"(acc[am][an][2]), "+f"(acc[am][an][3])
                        : "r"(a[am][0]), "r"(a[am][1]), "r"(a[am][2]), "r"(a[am][3]),
                          "r"(br[an16][hf * 2]), "r"(br[an16][hf * 2 + 1]));
                }
        }

        // epilogue: c0:(g,2t) c1:(g,2t+1) c2:(g+8,2t) c3:(g+8,2t+1)
        #pragma unroll
        for (int am = 0; am < 2; am++) {
            int r0a = row0 + wm * 32 + am * 16;
            int rA = r0a + g;
            int rB = r0a + g + 8;
            float sA = 1.0f, sB = 1.0f;
            if (use_scale) {
                if (rA < NN) sA = d_dinv[rA];
                if (rB < NN) sB = d_dinv[rB];
            }
            #pragma unroll
            for (int an = 0; an < 4; an++) {
                int col = wn * 32 + an * 8 + 2 * t;
                float bx = bias ? bias[col]     : 0.0f;
                float by = bias ? bias[col + 1] : 0.0f;
                if (rA < NN) {
                    float2 o;
                    o.x = (acc[am][an][0] + bx) * sA;
                    o.y = (acc[am][an][1] + by) * sA;
                    *(float2*)(C + (size_t)rA * HH + col) = o;
                }
                if (rB < NN) {
                    float2 o;
                    o.x = (acc[am][an][2] + bx) * sB;
                    o.y = (acc[am][an][3] + by) * sB;
                    *(float2*)(C + (size_t)rB * HH + col) = o;
                }
            }
        }
        __syncthreads();   // all LDSM done before next tile overwrites As16
    }
}

// ---------------- neighborhood aggregation (warp per node, MLP=4, fp32) --------
__global__ __launch_bounds__(256) void aggregate_kernel(
    const float* __restrict__ bias, int relu, int outsel)
{
    int node = blockIdx.x * 8 + (threadIdx.x >> 5);
    if (node >= NN) return;
    int lane = threadIdx.x & 31;
    float* out = (outsel == 1) ? d_h0 : d_h1;

    const float4* g4 = (const float4*)d_g;
    float4 acc = g4[(size_t)node * 32 + lane];   // self term

    int s = d_rowptr[node], e = d_rowptr[node + 1];
    int j = s;
    for (; j + 3 < e; j += 4) {
        int s0 = d_esrc[j], s1 = d_esrc[j + 1], s2 = d_esrc[j + 2], s3 = d_esrc[j + 3];
        float4 v0 = g4[(size_t)s0 * 32 + lane];
        float4 v1 = g4[(size_t)s1 * 32 + lane];
        float4 v2 = g4[(size_t)s2 * 32 + lane];
        float4 v3 = g4[(size_t)s3 * 32 + lane];
        acc.x += v0.x + v1.x + v2.x + v3.x;
        acc.y += v0.y + v1.y + v2.y + v3.y;
        acc.z += v0.z + v1.z + v2.z + v3.z;
        acc.w += v0.w + v1.w + v2.w + v3.w;
    }
    for (; j < e; j++) {
        int ss = d_esrc[j];
        float4 v = g4[(size_t)ss * 32 + lane];
        acc.x += v.x; acc.y += v.y; acc.z += v.z; acc.w += v.w;
    }

    float di = d_dinv[node];
    float4 b4 = ((const float4*)bias)[lane];
    float4 o;
    o.x = fmaf(acc.x, di, b4.x);
    o.y = fmaf(acc.y, di, b4.y);
    o.z = fmaf(acc.z, di, b4.z);
    o.w = fmaf(acc.w, di, b4.w);
    if (relu) {
        o.x = fmaxf(o.x, 0.f); o.y = fmaxf(o.y, 0.f);
        o.z = fmaxf(o.z, 0.f); o.w = fmaxf(o.w, 0.f);
    }
    ((float4*)out)[(size_t)node * 32 + lane] = o;
}

// ---------------- fused last-hop aggregation + classifier + pool ----------------
__global__ __launch_bounds__(256) void aggregate_cls_kernel(
    const float* __restrict__ bias, const int* __restrict__ batch,
    const float* __restrict__ Wc, const float* __restrict__ bc)
{
    __shared__ float sW[HH * OUTD];
    __shared__ float sB[OUTD];
    int tid = threadIdx.x;
    for (int i = tid; i < HH * OUTD; i += 256) sW[i] = Wc[i];
    if (tid < OUTD) sB[tid] = bc[tid];
    __syncthreads();

    int node = blockIdx.x * 8 + (tid >> 5);
    if (node >= NN) return;
    int lane = tid & 31;

    const float4* g4 = (const float4*)d_g;
    float4 acc = g4[(size_t)node * 32 + lane];

    int s = d_rowptr[node], e = d_rowptr[node + 1];
    int j = s;
    for (; j + 3 < e; j += 4) {
        int s0 = d_esrc[j], s1 = d_esrc[j + 1], s2 = d_esrc[j + 2], s3 = d_esrc[j + 3];
        float4 v0 = g4[(size_t)s0 * 32 + lane];
        float4 v1 = g4[(size_t)s1 * 32 + lane];
        float4 v2 = g4[(size_t)s2 * 32 + lane];
        float4 v3 = g4[(size_t)s3 * 32 + lane];
        acc.x += v0.x + v1.x + v2.x + v3.x;
        acc.y += v0.y + v1.y + v2.y + v3.y;
        acc.z += v0.z + v1.z + v2.z + v3.z;
        acc.w += v0.w + v1.w + v2.w + v3.w;
    }
    for (; j < e; j++) {
        int ss = d_esrc[j];
        float4 v = g4[(size_t)ss * 32 + lane];
        acc.x += v.x; acc.y += v.y; acc.z += v.z; acc.w += v.w;
    }

    float di = d_dinv[node];
    float4 b4 = ((const float4*)bias)[lane];
    float4 o;                      // cols 4*lane .. 4*lane+3 (no relu on last hop)
    o.x = fmaf(acc.x, di, b4.x);
    o.y = fmaf(acc.y, di, b4.y);
    o.z = fmaf(acc.z, di, b4.z);
    o.w = fmaf(acc.w, di, b4.w);

    int c0 = 4 * lane;
    float p[OUTD];
    #pragma unroll
    for (int d = 0; d < OUTD; d++) {
        float v = o.x * sW[(c0 + 0) * OUTD + d];
        v = fmaf(o.y, sW[(c0 + 1) * OUTD + d], v);
        v = fmaf(o.z, sW[(c0 + 2) * OUTD + d], v);
        v = fmaf(o.w, sW[(c0 + 3) * OUTD + d], v);
        p[d] = v;
    }
    #pragma unroll
    for (int off = 16; off > 0; off >>= 1) {
        #pragma unroll
        for (int d = 0; d < OUTD; d++)
            p[d] += __shfl_xor_sync(0xffffffffu, p[d], off);
    }
    int st = d_stride;
    int b = clampi(batch[(size_t)st * node], 0, GG - 1);
    if (lane < OUTD) {
        float v = p[0];
        #pragma unroll
        for (int d = 1; d < OUTD; d++) v = (lane == d) ? p[d] : v;
        atomicAdd(&d_sums[b * OUTD + lane], v + sB[lane]);
    }
    if (lane == OUTD) atomicAdd(&d_cnt[b], 1.0f);
}

// ---------------- final divide ----------------
__global__ void finalize_kernel(float* __restrict__ out) {
    int i = blockIdx.x * blockDim.x + threadIdx.x;
    if (i < GG * OUTD) {
        float c = d_cnt[i / OUTD];
        out[i] = d_sums[i] / fmaxf(c, 1.0f);
    }
}

// ---------------- launch ----------------
extern "C" void kernel_launch(void* const* d_in, const int* in_sizes, int n_in,
                              void* d_out, int out_size) {
    const float* x      = (const float*)d_in[0];
    const int*   ei     = (const int*)d_in[1];
    const int*   batch  = (const int*)d_in[2];
    const float* W_in   = (const float*)d_in[3];
    const float* b_in   = (const float*)d_in[4];
    const float* W_hops = (const float*)d_in[5];
    const float* b_hops = (const float*)d_in[6];
    const float* W_cls  = (const float*)d_in[7];
    const float* b_cls  = (const float*)d_in[8];
    float* out = (float*)d_out;

    const int GB2 = (NN + 127) / 128;   // 391 blocks, 2 tiles each

    detect_kernel<<<1, 128>>>(ei);
    zero_kernel<<<(NN + 255) / 256, 256>>>();
    count_kernel<<<(EE + 255) / 256, 256>>>(ei);
    // encoder GEMM in slot 4 for stable ncu sampling
    gemm_f16_kernel<<<GB2, 256>>>(x, W_in, b_in, 0, 0, 1);
    scanA_kernel<<<NB, 256>>>();
    scanB_kernel<<<1, 256>>>();
    scanC_kernel<<<NB, 256>>>();
    scatter_kernel<<<(EE + 255) / 256, 256>>>(ei);

    int cur = 1;   // d_h0
    for (int hop = 0; hop < NHOPS; hop++) {
        int nxt = (cur == 1) ? 2 : 1;
        gemm_f16_kernel<<<GB2, 256>>>(nullptr, W_hops + (size_t)hop * HH * HH,
                                      nullptr, cur, 1, 0);
        if (hop < NHOPS - 1) {
            aggregate_kernel<<<(NN + 7) / 8, 256>>>(b_hops + hop * HH, 1, nxt);
        } else {
            aggregate_cls_kernel<<<(NN + 7) / 8, 256>>>(b_hops + hop * HH,
                                                        batch, W_cls, b_cls);
        }
        cur = nxt;
    }

    finalize_kernel<<<(GG * OUTD + 255) / 256, 256>>>(out);
}

// round 15
// speedup vs baseline: 1.6139x; 1.0189x over previous
#include <cuda_runtime.h>
#include <cuda_fp16.h>
#include <cstdint>

#define NN    50000
#define EE    800000
#define HH    128
#define GG    128
#define OUTD  10
#define NHOPS 4
#define NB    ((NN + 255) / 256)   // 196 scan blocks
#define GEMM_GRID 296              // 2 blocks per SM (148 SMs)

// ---------------- device scratch (static, no runtime allocation) ----------------
__device__ __align__(16) float d_h0[NN * HH];
__device__ __align__(16) float d_h1[NN * HH];
__device__ __align__(16) float d_g[NN * HH];
__device__ float d_dinv[NN];
__device__ int   d_degcnt[NN];
__device__ int   d_rowptr[NN + 1];
__device__ int   d_cursor[NN];
__device__ int   d_esrc[EE];
__device__ float d_sums[GG * OUTD];
__device__ float d_cnt[GG];
__device__ int   d_stride;     // 1 = int32 inputs, 2 = int64 inputs
__device__ int   d_blksum[NB];
__device__ int   d_blkoff[NB];

__device__ __forceinline__ int clampi(int v, int lo, int hi) {
    return v < lo ? lo : (v > hi ? hi : v);
}

__device__ __forceinline__ uint32_t packh2(float a, float b) {
    __half2 h = __floats2half2_rn(a, b);
    return *(uint32_t*)&h;
}

// ---------------- dtype detection: int32 vs int64 edge_index -------------------
__global__ void detect_kernel(const int* __restrict__ ei_words) {
    __shared__ int nonzero;
    if (threadIdx.x == 0) nonzero = 0;
    __syncthreads();
    int w = ei_words[2 * threadIdx.x + 1];
    if (w != 0) atomicOr(&nonzero, 1);
    __syncthreads();
    if (threadIdx.x == 0) d_stride = nonzero ? 1 : 2;
}

// ---------------- zero per-launch state ----------------
__global__ void zero_kernel() {
    int i = blockIdx.x * blockDim.x + threadIdx.x;
    if (i < NN) { d_degcnt[i] = 0; d_cursor[i] = 0; }
    if (i < GG * OUTD) d_sums[i] = 0.0f;
    if (i < GG) d_cnt[i] = 0.0f;
}

// ---------------- in-degree count ----------------
__global__ void count_kernel(const int* __restrict__ ei) {
    int e = blockIdx.x * blockDim.x + threadIdx.x;
    if (e < EE) {
        int st = d_stride;
        int dst = clampi(ei[(size_t)st * (EE + e)], 0, NN - 1);
        atomicAdd(&d_degcnt[dst], 1);
    }
}

// ---------------- scan stages ----------------
__global__ __launch_bounds__(256) void scanA_kernel() {
    int i = blockIdx.x * 256 + threadIdx.x;
    int v = (i < NN) ? d_degcnt[i] : 0;
    int lane = threadIdx.x & 31, wid = threadIdx.x >> 5;
    int s = v;
    #pragma unroll
    for (int o = 16; o > 0; o >>= 1) s += __shfl_down_sync(0xffffffffu, s, o);
    __shared__ int ws[8];
    if (lane == 0) ws[wid] = s;
    __syncthreads();
    if (threadIdx.x == 0) {
        int t = 0;
        #pragma unroll
        for (int w = 0; w < 8; w++) t += ws[w];
        d_blksum[blockIdx.x] = t;
    }
}

__global__ __launch_bounds__(256) void scanB_kernel() {
    __shared__ int s_a[256], s_b[256];
    int t = threadIdx.x;
    int v = (t < NB) ? d_blksum[t] : 0;
    s_a[t] = v;
    __syncthreads();
    int* cur = s_a; int* nxt = s_b;
    for (int off = 1; off < 256; off <<= 1) {
        int x = cur[t];
        if (t >= off) x += cur[t - off];
        nxt[t] = x;
        __syncthreads();
        int* tmp = cur; cur = nxt; nxt = tmp;
    }
    if (t < NB) d_blkoff[t] = cur[t] - v;
    if (t == 0) d_rowptr[NN] = EE;
}

__global__ __launch_bounds__(256) void scanC_kernel() {
    int i = blockIdx.x * 256 + threadIdx.x;
    int v = (i < NN) ? d_degcnt[i] : 0;
    int lane = threadIdx.x & 31, wid = threadIdx.x >> 5;
    int incl = v;
    #pragma unroll
    for (int o = 1; o < 32; o <<= 1) {
        int y = __shfl_up_sync(0xffffffffu, incl, o);
        if (lane >= o) incl += y;
    }
    __shared__ int ws[8];
    if (lane == 31) ws[wid] = incl;
    __syncthreads();
    int woff = 0;
    #pragma unroll
    for (int w = 0; w < 8; w++) woff += (w < wid) ? ws[w] : 0;
    if (i < NN) {
        d_rowptr[i] = d_blkoff[blockIdx.x] + woff + incl - v;
        d_dinv[i] = rsqrtf(1.0f + (float)v);
    }
}

// ---------------- scatter edges into CSR buckets ----------------
__global__ void scatter_kernel(const int* __restrict__ ei) {
    int e = blockIdx.x * blockDim.x + threadIdx.x;
    if (e < EE) {
        int st = d_stride;
        int dst = clampi(ei[(size_t)st * (EE + e)], 0, NN - 1);
        int src = clampi(ei[(size_t)st * e],        0, NN - 1);
        int pos = d_rowptr[dst] + atomicAdd(&d_cursor[dst], 1);
        if (pos >= 0 && pos < EE) d_esrc[pos] = src;
    }
}

// ---------------- FP16 tensor-core GEMM v6 -------------------------------------
// Persistent-ish: grid 296 (2 blocks/SM), each block stages B ONCE and loops
// tiles blockIdx.x + 296*i with register-prefetched A staging (next tile's A
// loads issued before this tile's mainloop). Mainloop = pure LDSM + HMMA.
__global__ __launch_bounds__(256, 2) void gemm_f16_kernel(
    const float* __restrict__ Aext, const float* __restrict__ B,
    const float* __restrict__ bias, int asel, int use_scale, int csel)
{
    __shared__ uint4 As16[64 * 16];    // 16 KB
    __shared__ uint4 Bs16[128 * 16];   // 32 KB

    const float* A = (asel == 0) ? Aext : (asel == 1 ? d_h0 : d_h1);
    float* C = (csel == 0) ? d_g : (csel == 1 ? d_h0 : d_h1);

    int tid = threadIdx.x;
    int wid = tid >> 5, lane = tid & 31;
    int g = lane >> 2, t = lane & 3;
    int wm = wid & 1, wn = wid >> 1;        // warp grid 2 m x 4 n
    const float4* A4 = (const float4*)A;
    const float4* B4 = (const float4*)B;

    // stage B once: 2048 units, 8 per thread
    #pragma unroll
    for (int i = 0; i < 8; i++) {
        int idx = i * 256 + tid;
        int r = idx >> 4, u = idx & 15;
        float4 v0 = B4[(size_t)r * 32 + u * 2];
        float4 v1 = B4[(size_t)r * 32 + u * 2 + 1];
        uint4 h;
        h.x = packh2(v0.x, v0.y); h.y = packh2(v0.z, v0.w);
        h.z = packh2(v1.x, v1.y); h.w = packh2(v1.z, v1.w);
        Bs16[r * 16 + (u ^ (r & 7))] = h;
    }

    // lane decode for ldmatrix (loop-invariant)
    int cg = lane >> 4;
    int l7 = lane & 7;
    int l15 = lane & 15;
    uint32_t Abase = (uint32_t)__cvta_generic_to_shared(As16);
    uint32_t Bbase = (uint32_t)__cvta_generic_to_shared(Bs16);
    uint32_t arow[2];
    #pragma unroll
    for (int am = 0; am < 2; am++)
        arow[am] = Abase + (uint32_t)(wm * 32 + am * 16 + l15) * 256u;
    uint32_t bbase[2];
    #pragma unroll
    for (int an16 = 0; an16 < 2; an16++) {
        uint32_t up = (uint32_t)((wn * 4 + an16 * 2 + cg) ^ l7);
        bbase[an16] = Bbase + (uint32_t)l15 * 256u + up * 16u;
    }

    const int NT = (NN + 63) / 64;   // 782 tiles

    // prologue: prefetch A of first tile into registers
    float4 pf[8];
    int tt = blockIdx.x;
    if (tt < NT) {
        #pragma unroll
        for (int i = 0; i < 4; i++) {
            int idx = i * 256 + tid;
            int r = idx >> 4, u = idx & 15;
            int row = tt * 64 + r;
            if (row < NN) {
                pf[2 * i]     = A4[(size_t)row * 32 + u * 2];
                pf[2 * i + 1] = A4[(size_t)row * 32 + u * 2 + 1];
            } else {
                pf[2 * i] = pf[2 * i + 1] = make_float4(0.f, 0.f, 0.f, 0.f);
            }
        }
    }

    while (tt < NT) {
        // commit prefetched A to smem
        #pragma unroll
        for (int i = 0; i < 4; i++) {
            int idx = i * 256 + tid;
            int r = idx >> 4, u = idx & 15;
            uint4 h;
            h.x = packh2(pf[2 * i].x,     pf[2 * i].y);
            h.y = packh2(pf[2 * i].z,     pf[2 * i].w);
            h.z = packh2(pf[2 * i + 1].x, pf[2 * i + 1].y);
            h.w = packh2(pf[2 * i + 1].z, pf[2 * i + 1].w);
            As16[r * 16 + (u ^ (r & 7))] = h;
        }
        __syncthreads();

        int row0 = tt * 64;
        int nxt = tt + GEMM_GRID;
        // prefetch next tile's A (overlaps with compute below)
        if (nxt < NT) {
            #pragma unroll
            for (int i = 0; i < 4; i++) {
                int idx = i * 256 + tid;
                int r = idx >> 4, u = idx & 15;
                int row = nxt * 64 + r;
                if (row < NN) {
                    pf[2 * i]     = A4[(size_t)row * 32 + u * 2];
                    pf[2 * i + 1] = A4[(size_t)row * 32 + u * 2 + 1];
                } else {
                    pf[2 * i] = pf[2 * i + 1] = make_float4(0.f, 0.f, 0.f, 0.f);
                }
            }
        }

        float acc[2][4][4];
        #pragma unroll
        for (int am = 0; am < 2; am++)
            #pragma unroll
            for (int an = 0; an < 4; an++)
                #pragma unroll
                for (int q = 0; q < 4; q++) acc[am][an][q] = 0.0f;

        #pragma unroll
        for (int kc = 0; kc < 8; kc++) {
            uint32_t ua = (uint32_t)(((kc * 2 + cg) ^ l7) * 16);

            uint32_t a[2][4];
            #pragma unroll
            for (int am = 0; am < 2; am++) {
                asm volatile(
                    "ldmatrix.sync.aligned.m8n8.x4.shared.b16 {%0,%1,%2,%3}, [%4];"
                    : "=r"(a[am][0]), "=r"(a[am][1]), "=r"(a[am][2]), "=r"(a[am][3])
                    : "r"(arow[am] + ua));
            }
            uint32_t br[2][4];
            #pragma unroll
            for (int an16 = 0; an16 < 2; an16++) {
                asm volatile(
                    "ldmatrix.sync.aligned.m8n8.x4.trans.shared.b16 {%0,%1,%2,%3}, [%4];"
                    : "=r"(br[an16][0]), "=r"(br[an16][1]), "=r"(br[an16][2]), "=r"(br[an16][3])
                    : "r"(bbase[an16] + (uint32_t)kc * 4096u));
            }
            #pragma unroll
            for (int am = 0; am < 2; am++)
                #pragma unroll
                for (int an = 0; an < 4; an++) {
                    int an16 = an >> 1, hf = an & 1;
                    asm volatile(
                        "mma.sync.aligned.m16n8k16.row.col.f32.f16.f16.f32 "
                        "{%0,%1,%2,%3}, {%4,%5,%6,%7}, {%8,%9}, {%0,%1,%2,%3};"
                        : "+f"(acc[am][an][0]), "+f"(acc[am][an][1]),
                          "+f"(acc[am][an][2]), "+f"(acc[am][an][3])
                        : "r"(a[am][0]), "r"(a[am][1]), "r"(a[am][2]), "r"(a[am][3]),
                          "r"(br[an16][hf * 2]), "r"(br[an16][hf * 2 + 1]));
                }
        }

        // epilogue
        #pragma unroll
        for (int am = 0; am < 2; am++) {
            int r0a = row0 + wm * 32 + am * 16;
            int rA = r0a + g;
            int rB = r0a + g + 8;
            float sA = 1.0f, sB = 1.0f;
            if (use_scale) {
                if (rA < NN) sA = d_dinv[rA];
                if (rB < NN) sB = d_dinv[rB];
            }
            #pragma unroll
            for (int an = 0; an < 4; an++) {
                int col = wn * 32 + an * 8 + 2 * t;
                float bx = bias ? bias[col]     : 0.0f;
                float by = bias ? bias[col + 1] : 0.0f;
                if (rA < NN) {
                    float2 o;
                    o.x = (acc[am][an][0] + bx) * sA;
                    o.y = (acc[am][an][1] + by) * sA;
                    *(float2*)(C + (size_t)rA * HH + col) = o;
                }
                if (rB < NN) {
                    float2 o;
                    o.x = (acc[am][an][2] + bx) * sB;
                    o.y = (acc[am][an][3] + by) * sB;
                    *(float2*)(C + (size_t)rB * HH + col) = o;
                }
            }
        }
        __syncthreads();   // all LDSM done before next iteration's STS
        tt = nxt;
    }
}

// ---------------- neighborhood aggregation (warp per node, MLP=4, fp32) --------
__global__ __launch_bounds__(256) void aggregate_kernel(
    const float* __restrict__ bias, int relu, int outsel)
{
    int node = blockIdx.x * 8 + (threadIdx.x >> 5);
    if (node >= NN) return;
    int lane = threadIdx.x & 31;
    float* out = (outsel == 1) ? d_h0 : d_h1;

    const float4* g4 = (const float4*)d_g;
    float4 acc = g4[(size_t)node * 32 + lane];   // self term

    int s = d_rowptr[node], e = d_rowptr[node + 1];
    int j = s;
    for (; j + 3 < e; j += 4) {
        int s0 = d_esrc[j], s1 = d_esrc[j + 1], s2 = d_esrc[j + 2], s3 = d_esrc[j + 3];
        float4 v0 = g4[(size_t)s0 * 32 + lane];
        float4 v1 = g4[(size_t)s1 * 32 + lane];
        float4 v2 = g4[(size_t)s2 * 32 + lane];
        float4 v3 = g4[(size_t)s3 * 32 + lane];
        acc.x += v0.x + v1.x + v2.x + v3.x;
        acc.y += v0.y + v1.y + v2.y + v3.y;
        acc.z += v0.z + v1.z + v2.z + v3.z;
        acc.w += v0.w + v1.w + v2.w + v3.w;
    }
    for (; j < e; j++) {
        int ss = d_esrc[j];
        float4 v = g4[(size_t)ss * 32 + lane];
        acc.x += v.x; acc.y += v.y; acc.z += v.z; acc.w += v.w;
    }

    float di = d_dinv[node];
    float4 b4 = ((const float4*)bias)[lane];
    float4 o;
    o.x = fmaf(acc.x, di, b4.x);
    o.y = fmaf(acc.y, di, b4.y);
    o.z = fmaf(acc.z, di, b4.z);
    o.w = fmaf(acc.w, di, b4.w);
    if (relu) {
        o.x = fmaxf(o.x, 0.f); o.y = fmaxf(o.y, 0.f);
        o.z = fmaxf(o.z, 0.f); o.w = fmaxf(o.w, 0.f);
    }
    ((float4*)out)[(size_t)node * 32 + lane] = o;
}

// ---------------- fused last-hop aggregation + classifier + pool ----------------
__global__ __launch_bounds__(256) void aggregate_cls_kernel(
    const float* __restrict__ bias, const int* __restrict__ batch,
    const float* __restrict__ Wc, const float* __restrict__ bc)
{
    __shared__ float sW[HH * OUTD];
    __shared__ float sB[OUTD];
    int tid = threadIdx.x;
    for (int i = tid; i < HH * OUTD; i += 256) sW[i] = Wc[i];
    if (tid < OUTD) sB[tid] = bc[tid];
    __syncthreads();

    int node = blockIdx.x * 8 + (tid >> 5);
    if (node >= NN) return;
    int lane = tid & 31;

    const float4* g4 = (const float4*)d_g;
    float4 acc = g4[(size_t)node * 32 + lane];

    int s = d_rowptr[node], e = d_rowptr[node + 1];
    int j = s;
    for (; j + 3 < e; j += 4) {
        int s0 = d_esrc[j], s1 = d_esrc[j + 1], s2 = d_esrc[j + 2], s3 = d_esrc[j + 3];
        float4 v0 = g4[(size_t)s0 * 32 + lane];
        float4 v1 = g4[(size_t)s1 * 32 + lane];
        float4 v2 = g4[(size_t)s2 * 32 + lane];
        float4 v3 = g4[(size_t)s3 * 32 + lane];
        acc.x += v0.x + v1.x + v2.x + v3.x;
        acc.y += v0.y + v1.y + v2.y + v3.y;
        acc.z += v0.z + v1.z + v2.z + v3.z;
        acc.w += v0.w + v1.w + v2.w + v3.w;
    }
    for (; j < e; j++) {
        int ss = d_esrc[j];
        float4 v = g4[(size_t)ss * 32 + lane];
        acc.x += v.x; acc.y += v.y; acc.z += v.z; acc.w += v.w;
    }

    float di = d_dinv[node];
    float4 b4 = ((const float4*)bias)[lane];
    float4 o;                      // cols 4*lane .. 4*lane+3 (no relu on last hop)
    o.x = fmaf(acc.x, di, b4.x);
    o.y = fmaf(acc.y, di, b4.y);
    o.z = fmaf(acc.z, di, b4.z);
    o.w = fmaf(acc.w, di, b4.w);

    int c0 = 4 * lane;
    float p[OUTD];
    #pragma unroll
    for (int d = 0; d < OUTD; d++) {
        float v = o.x * sW[(c0 + 0) * OUTD + d];
        v = fmaf(o.y, sW[(c0 + 1) * OUTD + d], v);
        v = fmaf(o.z, sW[(c0 + 2) * OUTD + d], v);
        v = fmaf(o.w, sW[(c0 + 3) * OUTD + d], v);
        p[d] = v;
    }
    #pragma unroll
    for (int off = 16; off > 0; off >>= 1) {
        #pragma unroll
        for (int d = 0; d < OUTD; d++)
            p[d] += __shfl_xor_sync(0xffffffffu, p[d], off);
    }
    int st = d_stride;
    int b = clampi(batch[(size_t)st * node], 0, GG - 1);
    if (lane < OUTD) {
        float v = p[0];
        #pragma unroll
        for (int d = 1; d < OUTD; d++) v = (lane == d) ? p[d] : v;
        atomicAdd(&d_sums[b * OUTD + lane], v + sB[lane]);
    }
    if (lane == OUTD) atomicAdd(&d_cnt[b], 1.0f);
}

// ---------------- final divide ----------------
__global__ void finalize_kernel(float* __restrict__ out) {
    int i = blockIdx.x * blockDim.x + threadIdx.x;
    if (i < GG * OUTD) {
        float c = d_cnt[i / OUTD];
        out[i] = d_sums[i] / fmaxf(c, 1.0f);
    }
}

// ---------------- launch ----------------
extern "C" void kernel_launch(void* const* d_in, const int* in_sizes, int n_in,
                              void* d_out, int out_size) {
    const float* x      = (const float*)d_in[0];
    const int*   ei     = (const int*)d_in[1];
    const int*   batch  = (const int*)d_in[2];
    const float* W_in   = (const float*)d_in[3];
    const float* b_in   = (const float*)d_in[4];
    const float* W_hops = (const float*)d_in[5];
    const float* b_hops = (const float*)d_in[6];
    const float* W_cls  = (const float*)d_in[7];
    const float* b_cls  = (const float*)d_in[8];
    float* out = (float*)d_out;

    detect_kernel<<<1, 128>>>(ei);
    zero_kernel<<<(NN + 255) / 256, 256>>>();
    count_kernel<<<(EE + 255) / 256, 256>>>(ei);
    // encoder GEMM in slot 4 for stable ncu sampling
    gemm_f16_kernel<<<GEMM_GRID, 256>>>(x, W_in, b_in, 0, 0, 1);
    scanA_kernel<<<NB, 256>>>();
    scanB_kernel<<<1, 256>>>();
    scanC_kernel<<<NB, 256>>>();
    scatter_kernel<<<(EE + 255) / 256, 256>>>(ei);

    int cur = 1;   // d_h0
    for (int hop = 0; hop < NHOPS; hop++) {
        int nxt = (cur == 1) ? 2 : 1;
        gemm_f16_kernel<<<GEMM_GRID, 256>>>(nullptr, W_hops + (size_t)hop * HH * HH,
                                            nullptr, cur, 1, 0);
        if (hop < NHOPS - 1) {
            aggregate_kernel<<<(NN + 7) / 8, 256>>>(b_hops + hop * HH, 1, nxt);
        } else {
            aggregate_cls_kernel<<<(NN + 7) / 8, 256>>>(b_hops + hop * HH,
                                                        batch, W_cls, b_cls);
        }
        cur = nxt;
    }

    finalize_kernel<<<(GG * OUTD + 255) / 256, 256>>>(out);
}

// round 16
// speedup vs baseline: 1.7125x; 1.0611x over previous
#include <cuda_runtime.h>
#include <cuda_fp16.h>
#include <cstdint>

#define NN    50000
#define EE    800000
#define HH    128
#define GG    128
#define OUTD  10
#define NHOPS 4
#define NB    ((NN + 255) / 256)   // 196 scan blocks
#define GEMM_GRID 296              // 2 blocks per SM (148 SMs)

// ---------------- device scratch (static, no runtime allocation) ----------------
__device__ __align__(16) __half d_h0[NN * HH];   // fp16 activations
__device__ __align__(16) __half d_h1[NN * HH];
__device__ __align__(16) float  d_g[NN * HH];    // fp32 gather buffer
__device__ float d_dinv[NN];
__device__ int   d_degcnt[NN];
__device__ int   d_rowptr[NN + 1];
__device__ int   d_cursor[NN];
__device__ int   d_esrc[EE];
__device__ float d_sums[GG * OUTD];
__device__ float d_cnt[GG];
__device__ int   d_stride;     // 1 = int32 inputs, 2 = int64 inputs
__device__ int   d_blksum[NB];
__device__ int   d_blkoff[NB];

__device__ __forceinline__ int clampi(int v, int lo, int hi) {
    return v < lo ? lo : (v > hi ? hi : v);
}

__device__ __forceinline__ uint32_t packh2(float a, float b) {
    __half2 h = __floats2half2_rn(a, b);
    return *(uint32_t*)&h;
}

// ---------------- dtype detection: int32 vs int64 edge_index -------------------
__global__ void detect_kernel(const int* __restrict__ ei_words) {
    __shared__ int nonzero;
    if (threadIdx.x == 0) nonzero = 0;
    __syncthreads();
    int w = ei_words[2 * threadIdx.x + 1];
    if (w != 0) atomicOr(&nonzero, 1);
    __syncthreads();
    if (threadIdx.x == 0) d_stride = nonzero ? 1 : 2;
}

// ---------------- zero per-launch state ----------------
__global__ void zero_kernel() {
    int i = blockIdx.x * blockDim.x + threadIdx.x;
    if (i < NN) { d_degcnt[i] = 0; d_cursor[i] = 0; }
    if (i < GG * OUTD) d_sums[i] = 0.0f;
    if (i < GG) d_cnt[i] = 0.0f;
}

// ---------------- in-degree count ----------------
__global__ void count_kernel(const int* __restrict__ ei) {
    int e = blockIdx.x * blockDim.x + threadIdx.x;
    if (e < EE) {
        int st = d_stride;
        int dst = clampi(ei[(size_t)st * (EE + e)], 0, NN - 1);
        atomicAdd(&d_degcnt[dst], 1);
    }
}

// ---------------- scan stages ----------------
__global__ __launch_bounds__(256) void scanA_kernel() {
    int i = blockIdx.x * 256 + threadIdx.x;
    int v = (i < NN) ? d_degcnt[i] : 0;
    int lane = threadIdx.x & 31, wid = threadIdx.x >> 5;
    int s = v;
    #pragma unroll
    for (int o = 16; o > 0; o >>= 1) s += __shfl_down_sync(0xffffffffu, s, o);
    __shared__ int ws[8];
    if (lane == 0) ws[wid] = s;
    __syncthreads();
    if (threadIdx.x == 0) {
        int t = 0;
        #pragma unroll
        for (int w = 0; w < 8; w++) t += ws[w];
        d_blksum[blockIdx.x] = t;
    }
}

__global__ __launch_bounds__(256) void scanB_kernel() {
    __shared__ int s_a[256], s_b[256];
    int t = threadIdx.x;
    int v = (t < NB) ? d_blksum[t] : 0;
    s_a[t] = v;
    __syncthreads();
    int* cur = s_a; int* nxt = s_b;
    for (int off = 1; off < 256; off <<= 1) {
        int x = cur[t];
        if (t >= off) x += cur[t - off];
        nxt[t] = x;
        __syncthreads();
        int* tmp = cur; cur = nxt; nxt = tmp;
    }
    if (t < NB) d_blkoff[t] = cur[t] - v;
    if (t == 0) d_rowptr[NN] = EE;
}

__global__ __launch_bounds__(256) void scanC_kernel() {
    int i = blockIdx.x * 256 + threadIdx.x;
    int v = (i < NN) ? d_degcnt[i] : 0;
    int lane = threadIdx.x & 31, wid = threadIdx.x >> 5;
    int incl = v;
    #pragma unroll
    for (int o = 1; o < 32; o <<= 1) {
        int y = __shfl_up_sync(0xffffffffu, incl, o);
        if (lane >= o) incl += y;
    }
    __shared__ int ws[8];
    if (lane == 31) ws[wid] = incl;
    __syncthreads();
    int woff = 0;
    #pragma unroll
    for (int w = 0; w < 8; w++) woff += (w < wid) ? ws[w] : 0;
    if (i < NN) {
        d_rowptr[i] = d_blkoff[blockIdx.x] + woff + incl - v;
        d_dinv[i] = rsqrtf(1.0f + (float)v);
    }
}

// ---------------- scatter edges into CSR buckets ----------------
__global__ void scatter_kernel(const int* __restrict__ ei) {
    int e = blockIdx.x * blockDim.x + threadIdx.x;
    if (e < EE) {
        int st = d_stride;
        int dst = clampi(ei[(size_t)st * (EE + e)], 0, NN - 1);
        int src = clampi(ei[(size_t)st * e],        0, NN - 1);
        int pos = d_rowptr[dst] + atomicAdd(&d_cursor[dst], 1);
        if (pos >= 0 && pos < EE) d_esrc[pos] = src;
    }
}

// ---------------- encoder GEMM: h(fp16) = x(fp32) @ W_in + b_in ----------------
// Persistent, B staged once, register-prefetched A with f32->f16 cvt at staging.
__global__ __launch_bounds__(256, 2) void gemm_enc_kernel(
    const float* __restrict__ Aext, const float* __restrict__ B,
    const float* __restrict__ bias, int outsel)
{
    __shared__ uint4 As16[64 * 16];    // 16 KB
    __shared__ uint4 Bs16[128 * 16];   // 32 KB

    __half* C = (outsel == 1) ? d_h0 : d_h1;

    int tid = threadIdx.x;
    int wid = tid >> 5, lane = tid & 31;
    int g = lane >> 2, t = lane & 3;
    int wm = wid & 1, wn = wid >> 1;
    const float4* A4 = (const float4*)Aext;
    const float4* B4 = (const float4*)B;

    #pragma unroll
    for (int i = 0; i < 8; i++) {
        int idx = i * 256 + tid;
        int r = idx >> 4, u = idx & 15;
        float4 v0 = B4[(size_t)r * 32 + u * 2];
        float4 v1 = B4[(size_t)r * 32 + u * 2 + 1];
        uint4 h;
        h.x = packh2(v0.x, v0.y); h.y = packh2(v0.z, v0.w);
        h.z = packh2(v1.x, v1.y); h.w = packh2(v1.z, v1.w);
        Bs16[r * 16 + (u ^ (r & 7))] = h;
    }

    int cg = lane >> 4, l7 = lane & 7, l15 = lane & 15;
    uint32_t Abase = (uint32_t)__cvta_generic_to_shared(As16);
    uint32_t Bbase = (uint32_t)__cvta_generic_to_shared(Bs16);
    uint32_t arow[2];
    #pragma unroll
    for (int am = 0; am < 2; am++)
        arow[am] = Abase + (uint32_t)(wm * 32 + am * 16 + l15) * 256u;
    uint32_t bbase[2];
    #pragma unroll
    for (int an16 = 0; an16 < 2; an16++) {
        uint32_t up = (uint32_t)((wn * 4 + an16 * 2 + cg) ^ l7);
        bbase[an16] = Bbase + (uint32_t)l15 * 256u + up * 16u;
    }

    const int NT = (NN + 63) / 64;
    float4 pf[8];
    int tt = blockIdx.x;
    if (tt < NT) {
        #pragma unroll
        for (int i = 0; i < 4; i++) {
            int idx = i * 256 + tid;
            int r = idx >> 4, u = idx & 15;
            int row = tt * 64 + r;
            if (row < NN) {
                pf[2 * i]     = A4[(size_t)row * 32 + u * 2];
                pf[2 * i + 1] = A4[(size_t)row * 32 + u * 2 + 1];
            } else {
                pf[2 * i] = pf[2 * i + 1] = make_float4(0.f, 0.f, 0.f, 0.f);
            }
        }
    }

    while (tt < NT) {
        #pragma unroll
        for (int i = 0; i < 4; i++) {
            int idx = i * 256 + tid;
            int r = idx >> 4, u = idx & 15;
            uint4 h;
            h.x = packh2(pf[2 * i].x,     pf[2 * i].y);
            h.y = packh2(pf[2 * i].z,     pf[2 * i].w);
            h.z = packh2(pf[2 * i + 1].x, pf[2 * i + 1].y);
            h.w = packh2(pf[2 * i + 1].z, pf[2 * i + 1].w);
            As16[r * 16 + (u ^ (r & 7))] = h;
        }
        __syncthreads();

        int row0 = tt * 64;
        int nxt = tt + GEMM_GRID;
        if (nxt < NT) {
            #pragma unroll
            for (int i = 0; i < 4; i++) {
                int idx = i * 256 + tid;
                int r = idx >> 4, u = idx & 15;
                int row = nxt * 64 + r;
                if (row < NN) {
                    pf[2 * i]     = A4[(size_t)row * 32 + u * 2];
                    pf[2 * i + 1] = A4[(size_t)row * 32 + u * 2 + 1];
                } else {
                    pf[2 * i] = pf[2 * i + 1] = make_float4(0.f, 0.f, 0.f, 0.f);
                }
            }
        }

        float acc[2][4][4];
        #pragma unroll
        for (int am = 0; am < 2; am++)
            #pragma unroll
            for (int an = 0; an < 4; an++)
                #pragma unroll
                for (int q = 0; q < 4; q++) acc[am][an][q] = 0.0f;

        #pragma unroll
        for (int kc = 0; kc < 8; kc++) {
            uint32_t ua = (uint32_t)(((kc * 2 + cg) ^ l7) * 16);
            uint32_t a[2][4];
            #pragma unroll
            for (int am = 0; am < 2; am++) {
                asm volatile(
                    "ldmatrix.sync.aligned.m8n8.x4.shared.b16 {%0,%1,%2,%3}, [%4];"
                    : "=r"(a[am][0]), "=r"(a[am][1]), "=r"(a[am][2]), "=r"(a[am][3])
                    : "r"(arow[am] + ua));
            }
            uint32_t br[2][4];
            #pragma unroll
            for (int an16 = 0; an16 < 2; an16++) {
                asm volatile(
                    "ldmatrix.sync.aligned.m8n8.x4.trans.shared.b16 {%0,%1,%2,%3}, [%4];"
                    : "=r"(br[an16][0]), "=r"(br[an16][1]), "=r"(br[an16][2]), "=r"(br[an16][3])
                    : "r"(bbase[an16] + (uint32_t)kc * 4096u));
            }
            #pragma unroll
            for (int am = 0; am < 2; am++)
                #pragma unroll
                for (int an = 0; an < 4; an++) {
                    int an16 = an >> 1, hf = an & 1;
                    asm volatile(
                        "mma.sync.aligned.m16n8k16.row.col.f32.f16.f16.f32 "
                        "{%0,%1,%2,%3}, {%4,%5,%6,%7}, {%8,%9}, {%0,%1,%2,%3};"
                        : "+f"(acc[am][an][0]), "+f"(acc[am][an][1]),
                          "+f"(acc[am][an][2]), "+f"(acc[am][an][3])
                        : "r"(a[am][0]), "r"(a[am][1]), "r"(a[am][2]), "r"(a[am][3]),
                          "r"(br[an16][hf * 2]), "r"(br[an16][hf * 2 + 1]));
                }
        }

        // epilogue: write fp16 h
        __half2* Ch2 = (__half2*)C;
        #pragma unroll
        for (int am = 0; am < 2; am++) {
            int r0a = row0 + wm * 32 + am * 16;
            int rA = r0a + g;
            int rB = r0a + g + 8;
            #pragma unroll
            for (int an = 0; an < 4; an++) {
                int col = wn * 32 + an * 8 + 2 * t;
                float bx = bias[col], by = bias[col + 1];
                if (rA < NN)
                    Ch2[(size_t)rA * 64 + (col >> 1)] =
                        __floats2half2_rn(acc[am][an][0] + bx, acc[am][an][1] + by);
                if (rB < NN)
                    Ch2[(size_t)rB * 64 + (col >> 1)] =
                        __floats2half2_rn(acc[am][an][2] + bx, acc[am][an][3] + by);
            }
        }
        __syncthreads();
        tt = nxt;
    }
}

// ---------------- hop GEMM: g(fp32) = (h(fp16) @ W) * dinv[row] ----------------
// A staging is a raw uint4 copy (no cvt); prefetch = 4 uint4 (16 regs).
__global__ __launch_bounds__(256, 2) void gemm_hop_kernel(
    const float* __restrict__ B, int asel)
{
    __shared__ uint4 As16[64 * 16];    // 16 KB
    __shared__ uint4 Bs16[128 * 16];   // 32 KB

    const uint4* A4 = (const uint4*)((asel == 1) ? d_h0 : d_h1);  // row = 16 uint4
    float* C = d_g;

    int tid = threadIdx.x;
    int wid = tid >> 5, lane = tid & 31;
    int g = lane >> 2, t = lane & 3;
    int wm = wid & 1, wn = wid >> 1;
    const float4* B4 = (const float4*)B;

    #pragma unroll
    for (int i = 0; i < 8; i++) {
        int idx = i * 256 + tid;
        int r = idx >> 4, u = idx & 15;
        float4 v0 = B4[(size_t)r * 32 + u * 2];
        float4 v1 = B4[(size_t)r * 32 + u * 2 + 1];
        uint4 h;
        h.x = packh2(v0.x, v0.y); h.y = packh2(v0.z, v0.w);
        h.z = packh2(v1.x, v1.y); h.w = packh2(v1.z, v1.w);
        Bs16[r * 16 + (u ^ (r & 7))] = h;
    }

    int cg = lane >> 4, l7 = lane & 7, l15 = lane & 15;
    uint32_t Abase = (uint32_t)__cvta_generic_to_shared(As16);
    uint32_t Bbase = (uint32_t)__cvta_generic_to_shared(Bs16);
    uint32_t arow[2];
    #pragma unroll
    for (int am = 0; am < 2; am++)
        arow[am] = Abase + (uint32_t)(wm * 32 + am * 16 + l15) * 256u;
    uint32_t bbase[2];
    #pragma unroll
    for (int an16 = 0; an16 < 2; an16++) {
        uint32_t up = (uint32_t)((wn * 4 + an16 * 2 + cg) ^ l7);
        bbase[an16] = Bbase + (uint32_t)l15 * 256u + up * 16u;
    }

    const int NT = (NN + 63) / 64;
    uint4 pf[4];
    int tt = blockIdx.x;
    if (tt < NT) {
        #pragma unroll
        for (int i = 0; i < 4; i++) {
            int idx = i * 256 + tid;
            int r = idx >> 4, u = idx & 15;
            int row = tt * 64 + r;
            pf[i] = (row < NN) ? A4[(size_t)row * 16 + u]
                               : make_uint4(0u, 0u, 0u, 0u);
        }
    }

    while (tt < NT) {
        #pragma unroll
        for (int i = 0; i < 4; i++) {
            int idx = i * 256 + tid;
            int r = idx >> 4, u = idx & 15;
            As16[r * 16 + (u ^ (r & 7))] = pf[i];
        }
        __syncthreads();

        int row0 = tt * 64;
        int nxt = tt + GEMM_GRID;
        if (nxt < NT) {
            #pragma unroll
            for (int i = 0; i < 4; i++) {
                int idx = i * 256 + tid;
                int r = idx >> 4, u = idx & 15;
                int row = nxt * 64 + r;
                pf[i] = (row < NN) ? A4[(size_t)row * 16 + u]
                                   : make_uint4(0u, 0u, 0u, 0u);
            }
        }

        float acc[2][4][4];
        #pragma unroll
        for (int am = 0; am < 2; am++)
            #pragma unroll
            for (int an = 0; an < 4; an++)
                #pragma unroll
                for (int q = 0; q < 4; q++) acc[am][an][q] = 0.0f;

        #pragma unroll
        for (int kc = 0; kc < 8; kc++) {
            uint32_t ua = (uint32_t)(((kc * 2 + cg) ^ l7) * 16);
            uint32_t a[2][4];
            #pragma unroll
            for (int am = 0; am < 2; am++) {
                asm volatile(
                    "ldmatrix.sync.aligned.m8n8.x4.shared.b16 {%0,%1,%2,%3}, [%4];"
                    : "=r"(a[am][0]), "=r"(a[am][1]), "=r"(a[am][2]), "=r"(a[am][3])
                    : "r"(arow[am] + ua));
            }
            uint32_t br[2][4];
            #pragma unroll
            for (int an16 = 0; an16 < 2; an16++) {
                asm volatile(
                    "ldmatrix.sync.aligned.m8n8.x4.trans.shared.b16 {%0,%1,%2,%3}, [%4];"
                    : "=r"(br[an16][0]), "=r"(br[an16][1]), "=r"(br[an16][2]), "=r"(br[an16][3])
                    : "r"(bbase[an16] + (uint32_t)kc * 4096u));
            }
            #pragma unroll
            for (int am = 0; am < 2; am++)
                #pragma unroll
                for (int an = 0; an < 4; an++) {
                    int an16 = an >> 1, hf = an & 1;
                    asm volatile(
                        "mma.sync.aligned.m16n8k16.row.col.f32.f16.f16.f32 "
                        "{%0,%1,%2,%3}, {%4,%5,%6,%7}, {%8,%9}, {%0,%1,%2,%3};"
                        : "+f"(acc[am][an][0]), "+f"(acc[am][an][1]),
                          "+f"(acc[am][an][2]), "+f"(acc[am][an][3])
                        : "r"(a[am][0]), "r"(a[am][1]), "r"(a[am][2]), "r"(a[am][3]),
                          "r"(br[an16][hf * 2]), "r"(br[an16][hf * 2 + 1]));
                }
        }

        // epilogue: g = acc * dinv[row]
        #pragma unroll
        for (int am = 0; am < 2; am++) {
            int r0a = row0 + wm * 32 + am * 16;
            int rA = r0a + g;
            int rB = r0a + g + 8;
            float sA = (rA < NN) ? d_dinv[rA] : 0.0f;
            float sB = (rB < NN) ? d_dinv[rB] : 0.0f;
            #pragma unroll
            for (int an = 0; an < 4; an++) {
                int col = wn * 32 + an * 8 + 2 * t;
                if (rA < NN) {
                    float2 o;
                    o.x = acc[am][an][0] * sA;
                    o.y = acc[am][an][1] * sA;
                    *(float2*)(C + (size_t)rA * HH + col) = o;
                }
                if (rB < NN) {
                    float2 o;
                    o.x = acc[am][an][2] * sB;
                    o.y = acc[am][an][3] * sB;
                    *(float2*)(C + (size_t)rB * HH + col) = o;
                }
            }
        }
        __syncthreads();
        tt = nxt;
    }
}

// ---------------- neighborhood aggregation (fp32 g gather -> fp16 h write) -----
__global__ __launch_bounds__(256) void aggregate_kernel(
    const float* __restrict__ bias, int relu, int outsel)
{
    int node = blockIdx.x * 8 + (threadIdx.x >> 5);
    if (node >= NN) return;
    int lane = threadIdx.x & 31;
    __half* out = (outsel == 1) ? d_h0 : d_h1;

    const float4* g4 = (const float4*)d_g;
    float4 acc = g4[(size_t)node * 32 + lane];   // self term

    int s = d_rowptr[node], e = d_rowptr[node + 1];
    int j = s;
    for (; j + 3 < e; j += 4) {
        int s0 = d_esrc[j], s1 = d_esrc[j + 1], s2 = d_esrc[j + 2], s3 = d_esrc[j + 3];
        float4 v0 = g4[(size_t)s0 * 32 + lane];
        float4 v1 = g4[(size_t)s1 * 32 + lane];
        float4 v2 = g4[(size_t)s2 * 32 + lane];
        float4 v3 = g4[(size_t)s3 * 32 + lane];
        acc.x += v0.x + v1.x + v2.x + v3.x;
        acc.y += v0.y + v1.y + v2.y + v3.y;
        acc.z += v0.z + v1.z + v2.z + v3.z;
        acc.w += v0.w + v1.w + v2.w + v3.w;
    }
    for (; j < e; j++) {
        int ss = d_esrc[j];
        float4 v = g4[(size_t)ss * 32 + lane];
        acc.x += v.x; acc.y += v.y; acc.z += v.z; acc.w += v.w;
    }

    float di = d_dinv[node];
    float4 b4 = ((const float4*)bias)[lane];
    float4 o;
    o.x = fmaf(acc.x, di, b4.x);
    o.y = fmaf(acc.y, di, b4.y);
    o.z = fmaf(acc.z, di, b4.z);
    o.w = fmaf(acc.w, di, b4.w);
    if (relu) {
        o.x = fmaxf(o.x, 0.f); o.y = fmaxf(o.y, 0.f);
        o.z = fmaxf(o.z, 0.f); o.w = fmaxf(o.w, 0.f);
    }
    uint2 ov;
    ov.x = packh2(o.x, o.y);
    ov.y = packh2(o.z, o.w);
    ((uint2*)out)[(size_t)node * 32 + lane] = ov;
}

// ---------------- fused last-hop aggregation + classifier + pool ----------------
__global__ __launch_bounds__(256) void aggregate_cls_kernel(
    const float* __restrict__ bias, const int* __restrict__ batch,
    const float* __restrict__ Wc, const float* __restrict__ bc)
{
    __shared__ float sW[HH * OUTD];
    __shared__ float sB[OUTD];
    int tid = threadIdx.x;
    for (int i = tid; i < HH * OUTD; i += 256) sW[i] = Wc[i];
    if (tid < OUTD) sB[tid] = bc[tid];
    __syncthreads();

    int node = blockIdx.x * 8 + (tid >> 5);
    if (node >= NN) return;
    int lane = tid & 31;

    const float4* g4 = (const float4*)d_g;
    float4 acc = g4[(size_t)node * 32 + lane];

    int s = d_rowptr[node], e = d_rowptr[node + 1];
    int j = s;
    for (; j + 3 < e; j += 4) {
        int s0 = d_esrc[j], s1 = d_esrc[j + 1], s2 = d_esrc[j + 2], s3 = d_esrc[j + 3];
        float4 v0 = g4[(size_t)s0 * 32 + lane];
        float4 v1 = g4[(size_t)s1 * 32 + lane];
        float4 v2 = g4[(size_t)s2 * 32 + lane];
        float4 v3 = g4[(size_t)s3 * 32 + lane];
        acc.x += v0.x + v1.x + v2.x + v3.x;
        acc.y += v0.y + v1.y + v2.y + v3.y;
        acc.z += v0.z + v1.z + v2.z + v3.z;
        acc.w += v0.w + v1.w + v2.w + v3.w;
    }
    for (; j < e; j++) {
        int ss = d_esrc[j];
        float4 v = g4[(size_t)ss * 32 + lane];
        acc.x += v.x; acc.y += v.y; acc.z += v.z; acc.w += v.w;
    }

    float di = d_dinv[node];
    float4 b4 = ((const float4*)bias)[lane];
    float4 o;                      // cols 4*lane .. 4*lane+3 (no relu on last hop)
    o.x = fmaf(acc.x, di, b4.x);
    o.y = fmaf(acc.y, di, b4.y);
    o.z = fmaf(acc.z, di, b4.z);
    o.w = fmaf(acc.w, di, b4.w);

    int c0 = 4 * lane;
    float p[OUTD];
    #pragma unroll
    for (int d = 0; d < OUTD; d++) {
        float v = o.x * sW[(c0 + 0) * OUTD + d];
        v = fmaf(o.y, sW[(c0 + 1) * OUTD + d], v);
        v = fmaf(o.z, sW[(c0 + 2) * OUTD + d], v);
        v = fmaf(o.w, sW[(c0 + 3) * OUTD + d], v);
        p[d] = v;
    }
    #pragma unroll
    for (int off = 16; off > 0; off >>= 1) {
        #pragma unroll
        for (int d = 0; d < OUTD; d++)
            p[d] += __shfl_xor_sync(0xffffffffu, p[d], off);
    }
    int st = d_stride;
    int b = clampi(batch[(size_t)st * node], 0, GG - 1);
    if (lane < OUTD) {
        float v = p[0];
        #pragma unroll
        for (int d = 1; d < OUTD; d++) v = (lane == d) ? p[d] : v;
        atomicAdd(&d_sums[b * OUTD + lane], v + sB[lane]);
    }
    if (lane == OUTD) atomicAdd(&d_cnt[b], 1.0f);
}

// ---------------- final divide ----------------
__global__ void finalize_kernel(float* __restrict__ out) {
    int i = blockIdx.x * blockDim.x + threadIdx.x;
    if (i < GG * OUTD) {
        float c = d_cnt[i / OUTD];
        out[i] = d_sums[i] / fmaxf(c, 1.0f);
    }
}

// ---------------- launch ----------------
extern "C" void kernel_launch(void* const* d_in, const int* in_sizes, int n_in,
                              void* d_out, int out_size) {
    const float* x      = (const float*)d_in[0];
    const int*   ei     = (const int*)d_in[1];
    const int*   batch  = (const int*)d_in[2];
    const float* W_in   = (const float*)d_in[3];
    const float* b_in   = (const float*)d_in[4];
    const float* W_hops = (const float*)d_in[5];
    const float* b_hops = (const float*)d_in[6];
    const float* W_cls  = (const float*)d_in[7];
    const float* b_cls  = (const float*)d_in[8];
    float* out = (float*)d_out;

    detect_kernel<<<1, 128>>>(ei);
    zero_kernel<<<(NN + 255) / 256, 256>>>();
    count_kernel<<<(EE + 255) / 256, 256>>>(ei);
    // encoder GEMM in slot 4 for stable ncu sampling (writes fp16 h0)
    gemm_enc_kernel<<<GEMM_GRID, 256>>>(x, W_in, b_in, 1);
    scanA_kernel<<<NB, 256>>>();
    scanB_kernel<<<1, 256>>>();
    scanC_kernel<<<NB, 256>>>();
    scatter_kernel<<<(EE + 255) / 256, 256>>>(ei);

    int cur = 1;   // d_h0
    for (int hop = 0; hop < NHOPS; hop++) {
        int nxt = (cur == 1) ? 2 : 1;
        gemm_hop_kernel<<<GEMM_GRID, 256>>>(W_hops + (size_t)hop * HH * HH, cur);
        if (hop < NHOPS - 1) {
            aggregate_kernel<<<(NN + 7) / 8, 256>>>(b_hops + hop * HH, 1, nxt);
        } else {
            aggregate_cls_kernel<<<(NN + 7) / 8, 256>>>(b_hops + hop * HH,
                                                        batch, W_cls, b_cls);
        }
        cur = nxt;
    }

    finalize_kernel<<<(GG * OUTD + 255) / 256, 256>>>(out);
}

// round 17
// speedup vs baseline: 1.8171x; 1.0611x over previous
#include <cuda_runtime.h>
#include <cuda_fp16.h>
#include <cstdint>

#define NN    50000
#define EE    800000
#define HH    128
#define GG    128
#define OUTD  10
#define NHOPS 4
#define NB    ((NN + 255) / 256)   // 196 scan blocks
#define GEMM_GRID 296              // 2 blocks per SM (148 SMs)

// ---------------- device scratch (static, no runtime allocation) ----------------
__device__ __align__(16) __half d_h0[NN * HH];   // fp16 activations
__device__ __align__(16) __half d_h1[NN * HH];
__device__ __align__(16) __half d_g[NN * HH];    // fp16 gather buffer
__device__ float d_dinv[NN];
__device__ int   d_degcnt[NN];
__device__ int   d_rowptr[NN + 1];
__device__ int   d_cursor[NN];
__device__ int   d_esrc[EE];
__device__ float d_sums[GG * OUTD];
__device__ float d_cnt[GG];
__device__ int   d_stride;     // 1 = int32 inputs, 2 = int64 inputs
__device__ int   d_blksum[NB];
__device__ int   d_blkoff[NB];

__device__ __forceinline__ int clampi(int v, int lo, int hi) {
    return v < lo ? lo : (v > hi ? hi : v);
}

__device__ __forceinline__ uint32_t packh2(float a, float b) {
    __half2 h = __floats2half2_rn(a, b);
    return *(uint32_t*)&h;
}

// ---------------- dtype detection: int32 vs int64 edge_index -------------------
__global__ void detect_kernel(const int* __restrict__ ei_words) {
    __shared__ int nonzero;
    if (threadIdx.x == 0) nonzero = 0;
    __syncthreads();
    int w = ei_words[2 * threadIdx.x + 1];
    if (w != 0) atomicOr(&nonzero, 1);
    __syncthreads();
    if (threadIdx.x == 0) d_stride = nonzero ? 1 : 2;
}

// ---------------- zero per-launch state ----------------
__global__ void zero_kernel() {
    int i = blockIdx.x * blockDim.x + threadIdx.x;
    if (i < NN) { d_degcnt[i] = 0; d_cursor[i] = 0; }
    if (i < GG * OUTD) d_sums[i] = 0.0f;
    if (i < GG) d_cnt[i] = 0.0f;
}

// ---------------- in-degree count ----------------
__global__ void count_kernel(const int* __restrict__ ei) {
    int e = blockIdx.x * blockDim.x + threadIdx.x;
    if (e < EE) {
        int st = d_stride;
        int dst = clampi(ei[(size_t)st * (EE + e)], 0, NN - 1);
        atomicAdd(&d_degcnt[dst], 1);
    }
}

// ---------------- scan stages ----------------
__global__ __launch_bounds__(256) void scanA_kernel() {
    int i = blockIdx.x * 256 + threadIdx.x;
    int v = (i < NN) ? d_degcnt[i] : 0;
    int lane = threadIdx.x & 31, wid = threadIdx.x >> 5;
    int s = v;
    #pragma unroll
    for (int o = 16; o > 0; o >>= 1) s += __shfl_down_sync(0xffffffffu, s, o);
    __shared__ int ws[8];
    if (lane == 0) ws[wid] = s;
    __syncthreads();
    if (threadIdx.x == 0) {
        int t = 0;
        #pragma unroll
        for (int w = 0; w < 8; w++) t += ws[w];
        d_blksum[blockIdx.x] = t;
    }
}

__global__ __launch_bounds__(256) void scanB_kernel() {
    __shared__ int s_a[256], s_b[256];
    int t = threadIdx.x;
    int v = (t < NB) ? d_blksum[t] : 0;
    s_a[t] = v;
    __syncthreads();
    int* cur = s_a; int* nxt = s_b;
    for (int off = 1; off < 256; off <<= 1) {
        int x = cur[t];
        if (t >= off) x += cur[t - off];
        nxt[t] = x;
        __syncthreads();
        int* tmp = cur; cur = nxt; nxt = tmp;
    }
    if (t < NB) d_blkoff[t] = cur[t] - v;
    if (t == 0) d_rowptr[NN] = EE;
}

__global__ __launch_bounds__(256) void scanC_kernel() {
    int i = blockIdx.x * 256 + threadIdx.x;
    int v = (i < NN) ? d_degcnt[i] : 0;
    int lane = threadIdx.x & 31, wid = threadIdx.x >> 5;
    int incl = v;
    #pragma unroll
    for (int o = 1; o < 32; o <<= 1) {
        int y = __shfl_up_sync(0xffffffffu, incl, o);
        if (lane >= o) incl += y;
    }
    __shared__ int ws[8];
    if (lane == 31) ws[wid] = incl;
    __syncthreads();
    int woff = 0;
    #pragma unroll
    for (int w = 0; w < 8; w++) woff += (w < wid) ? ws[w] : 0;
    if (i < NN) {
        d_rowptr[i] = d_blkoff[blockIdx.x] + woff + incl - v;
        d_dinv[i] = rsqrtf(1.0f + (float)v);
    }
}

// ---------------- scatter edges into CSR buckets ----------------
__global__ void scatter_kernel(const int* __restrict__ ei) {
    int e = blockIdx.x * blockDim.x + threadIdx.x;
    if (e < EE) {
        int st = d_stride;
        int dst = clampi(ei[(size_t)st * (EE + e)], 0, NN - 1);
        int src = clampi(ei[(size_t)st * e],        0, NN - 1);
        int pos = d_rowptr[dst] + atomicAdd(&d_cursor[dst], 1);
        if (pos >= 0 && pos < EE) d_esrc[pos] = src;
    }
}

// ---------------- encoder GEMM: h(fp16) = x(fp32) @ W_in + b_in ----------------
__global__ __launch_bounds__(256, 2) void gemm_enc_kernel(
    const float* __restrict__ Aext, const float* __restrict__ B,
    const float* __restrict__ bias, int outsel)
{
    __shared__ uint4 As16[64 * 16];    // 16 KB
    __shared__ uint4 Bs16[128 * 16];   // 32 KB

    __half* C = (outsel == 1) ? d_h0 : d_h1;

    int tid = threadIdx.x;
    int wid = tid >> 5, lane = tid & 31;
    int g = lane >> 2, t = lane & 3;
    int wm = wid & 1, wn = wid >> 1;
    const float4* A4 = (const float4*)Aext;
    const float4* B4 = (const float4*)B;

    #pragma unroll
    for (int i = 0; i < 8; i++) {
        int idx = i * 256 + tid;
        int r = idx >> 4, u = idx & 15;
        float4 v0 = B4[(size_t)r * 32 + u * 2];
        float4 v1 = B4[(size_t)r * 32 + u * 2 + 1];
        uint4 h;
        h.x = packh2(v0.x, v0.y); h.y = packh2(v0.z, v0.w);
        h.z = packh2(v1.x, v1.y); h.w = packh2(v1.z, v1.w);
        Bs16[r * 16 + (u ^ (r & 7))] = h;
    }

    int cg = lane >> 4, l7 = lane & 7, l15 = lane & 15;
    uint32_t Abase = (uint32_t)__cvta_generic_to_shared(As16);
    uint32_t Bbase = (uint32_t)__cvta_generic_to_shared(Bs16);
    uint32_t arow[2];
    #pragma unroll
    for (int am = 0; am < 2; am++)
        arow[am] = Abase + (uint32_t)(wm * 32 + am * 16 + l15) * 256u;
    uint32_t bbase[2];
    #pragma unroll
    for (int an16 = 0; an16 < 2; an16++) {
        uint32_t up = (uint32_t)((wn * 4 + an16 * 2 + cg) ^ l7);
        bbase[an16] = Bbase + (uint32_t)l15 * 256u + up * 16u;
    }

    const int NT = (NN + 63) / 64;
    float4 pf[8];
    int tt = blockIdx.x;
    if (tt < NT) {
        #pragma unroll
        for (int i = 0; i < 4; i++) {
            int idx = i * 256 + tid;
            int r = idx >> 4, u = idx & 15;
            int row = tt * 64 + r;
            if (row < NN) {
                pf[2 * i]     = A4[(size_t)row * 32 + u * 2];
                pf[2 * i + 1] = A4[(size_t)row * 32 + u * 2 + 1];
            } else {
                pf[2 * i] = pf[2 * i + 1] = make_float4(0.f, 0.f, 0.f, 0.f);
            }
        }
    }

    while (tt < NT) {
        #pragma unroll
        for (int i = 0; i < 4; i++) {
            int idx = i * 256 + tid;
            int r = idx >> 4, u = idx & 15;
            uint4 h;
            h.x = packh2(pf[2 * i].x,     pf[2 * i].y);
            h.y = packh2(pf[2 * i].z,     pf[2 * i].w);
            h.z = packh2(pf[2 * i + 1].x, pf[2 * i + 1].y);
            h.w = packh2(pf[2 * i + 1].z, pf[2 * i + 1].w);
            As16[r * 16 + (u ^ (r & 7))] = h;
        }
        __syncthreads();

        int row0 = tt * 64;
        int nxt = tt + GEMM_GRID;
        if (nxt < NT) {
            #pragma unroll
            for (int i = 0; i < 4; i++) {
                int idx = i * 256 + tid;
                int r = idx >> 4, u = idx & 15;
                int row = nxt * 64 + r;
                if (row < NN) {
                    pf[2 * i]     = A4[(size_t)row * 32 + u * 2];
                    pf[2 * i + 1] = A4[(size_t)row * 32 + u * 2 + 1];
                } else {
                    pf[2 * i] = pf[2 * i + 1] = make_float4(0.f, 0.f, 0.f, 0.f);
                }
            }
        }

        float acc[2][4][4];
        #pragma unroll
        for (int am = 0; am < 2; am++)
            #pragma unroll
            for (int an = 0; an < 4; an++)
                #pragma unroll
                for (int q = 0; q < 4; q++) acc[am][an][q] = 0.0f;

        #pragma unroll
        for (int kc = 0; kc < 8; kc++) {
            uint32_t ua = (uint32_t)(((kc * 2 + cg) ^ l7) * 16);
            uint32_t a[2][4];
            #pragma unroll
            for (int am = 0; am < 2; am++) {
                asm volatile(
                    "ldmatrix.sync.aligned.m8n8.x4.shared.b16 {%0,%1,%2,%3}, [%4];"
                    : "=r"(a[am][0]), "=r"(a[am][1]), "=r"(a[am][2]), "=r"(a[am][3])
                    : "r"(arow[am] + ua));
            }
            uint32_t br[2][4];
            #pragma unroll
            for (int an16 = 0; an16 < 2; an16++) {
                asm volatile(
                    "ldmatrix.sync.aligned.m8n8.x4.trans.shared.b16 {%0,%1,%2,%3}, [%4];"
                    : "=r"(br[an16][0]), "=r"(br[an16][1]), "=r"(br[an16][2]), "=r"(br[an16][3])
                    : "r"(bbase[an16] + (uint32_t)kc * 4096u));
            }
            #pragma unroll
            for (int am = 0; am < 2; am++)
                #pragma unroll
                for (int an = 0; an < 4; an++) {
                    int an16 = an >> 1, hf = an & 1;
                    asm volatile(
                        "mma.sync.aligned.m16n8k16.row.col.f32.f16.f16.f32 "
                        "{%0,%1,%2,%3}, {%4,%5,%6,%7}, {%8,%9}, {%0,%1,%2,%3};"
                        : "+f"(acc[am][an][0]), "+f"(acc[am][an][1]),
                          "+f"(acc[am][an][2]), "+f"(acc[am][an][3])
                        : "r"(a[am][0]), "r"(a[am][1]), "r"(a[am][2]), "r"(a[am][3]),
                          "r"(br[an16][hf * 2]), "r"(br[an16][hf * 2 + 1]));
                }
        }

        __half2* Ch2 = (__half2*)C;
        #pragma unroll
        for (int am = 0; am < 2; am++) {
            int r0a = row0 + wm * 32 + am * 16;
            int rA = r0a + g;
            int rB = r0a + g + 8;
            #pragma unroll
            for (int an = 0; an < 4; an++) {
                int col = wn * 32 + an * 8 + 2 * t;
                float bx = bias[col], by = bias[col + 1];
                if (rA < NN)
                    Ch2[(size_t)rA * 64 + (col >> 1)] =
                        __floats2half2_rn(acc[am][an][0] + bx, acc[am][an][1] + by);
                if (rB < NN)
                    Ch2[(size_t)rB * 64 + (col >> 1)] =
                        __floats2half2_rn(acc[am][an][2] + bx, acc[am][an][3] + by);
            }
        }
        __syncthreads();
        tt = nxt;
    }
}

// ---------------- hop GEMM: g(fp16) = (h(fp16) @ W) * dinv[row] ----------------
__global__ __launch_bounds__(256, 2) void gemm_hop_kernel(
    const float* __restrict__ B, int asel)
{
    __shared__ uint4 As16[64 * 16];    // 16 KB
    __shared__ uint4 Bs16[128 * 16];   // 32 KB

    const uint4* A4 = (const uint4*)((asel == 1) ? d_h0 : d_h1);

    int tid = threadIdx.x;
    int wid = tid >> 5, lane = tid & 31;
    int g = lane >> 2, t = lane & 3;
    int wm = wid & 1, wn = wid >> 1;
    const float4* B4 = (const float4*)B;

    #pragma unroll
    for (int i = 0; i < 8; i++) {
        int idx = i * 256 + tid;
        int r = idx >> 4, u = idx & 15;
        float4 v0 = B4[(size_t)r * 32 + u * 2];
        float4 v1 = B4[(size_t)r * 32 + u * 2 + 1];
        uint4 h;
        h.x = packh2(v0.x, v0.y); h.y = packh2(v0.z, v0.w);
        h.z = packh2(v1.x, v1.y); h.w = packh2(v1.z, v1.w);
        Bs16[r * 16 + (u ^ (r & 7))] = h;
    }

    int cg = lane >> 4, l7 = lane & 7, l15 = lane & 15;
    uint32_t Abase = (uint32_t)__cvta_generic_to_shared(As16);
    uint32_t Bbase = (uint32_t)__cvta_generic_to_shared(Bs16);
    uint32_t arow[2];
    #pragma unroll
    for (int am = 0; am < 2; am++)
        arow[am] = Abase + (uint32_t)(wm * 32 + am * 16 + l15) * 256u;
    uint32_t bbase[2];
    #pragma unroll
    for (int an16 = 0; an16 < 2; an16++) {
        uint32_t up = (uint32_t)((wn * 4 + an16 * 2 + cg) ^ l7);
        bbase[an16] = Bbase + (uint32_t)l15 * 256u + up * 16u;
    }

    const int NT = (NN + 63) / 64;
    uint4 pf[4];
    int tt = blockIdx.x;
    if (tt < NT) {
        #pragma unroll
        for (int i = 0; i < 4; i++) {
            int idx = i * 256 + tid;
            int r = idx >> 4, u = idx & 15;
            int row = tt * 64 + r;
            pf[i] = (row < NN) ? A4[(size_t)row * 16 + u]
                               : make_uint4(0u, 0u, 0u, 0u);
        }
    }

    while (tt < NT) {
        #pragma unroll
        for (int i = 0; i < 4; i++) {
            int idx = i * 256 + tid;
            int r = idx >> 4, u = idx & 15;
            As16[r * 16 + (u ^ (r & 7))] = pf[i];
        }
        __syncthreads();

        int row0 = tt * 64;
        int nxt = tt + GEMM_GRID;
        if (nxt < NT) {
            #pragma unroll
            for (int i = 0; i < 4; i++) {
                int idx = i * 256 + tid;
                int r = idx >> 4, u = idx & 15;
                int row = nxt * 64 + r;
                pf[i] = (row < NN) ? A4[(size_t)row * 16 + u]
                                   : make_uint4(0u, 0u, 0u, 0u);
            }
        }

        float acc[2][4][4];
        #pragma unroll
        for (int am = 0; am < 2; am++)
            #pragma unroll
            for (int an = 0; an < 4; an++)
                #pragma unroll
                for (int q = 0; q < 4; q++) acc[am][an][q] = 0.0f;

        #pragma unroll
        for (int kc = 0; kc < 8; kc++) {
            uint32_t ua = (uint32_t)(((kc * 2 + cg) ^ l7) * 16);
            uint32_t a[2][4];
            #pragma unroll
            for (int am = 0; am < 2; am++) {
                asm volatile(
                    "ldmatrix.sync.aligned.m8n8.x4.shared.b16 {%0,%1,%2,%3}, [%4];"
                    : "=r"(a[am][0]), "=r"(a[am][1]), "=r"(a[am][2]), "=r"(a[am][3])
                    : "r"(arow[am] + ua));
            }
            uint32_t br[2][4];
            #pragma unroll
            for (int an16 = 0; an16 < 2; an16++) {
                asm volatile(
                    "ldmatrix.sync.aligned.m8n8.x4.trans.shared.b16 {%0,%1,%2,%3}, [%4];"
                    : "=r"(br[an16][0]), "=r"(br[an16][1]), "=r"(br[an16][2]), "=r"(br[an16][3])
                    : "r"(bbase[an16] + (uint32_t)kc * 4096u));
            }
            #pragma unroll
            for (int am = 0; am < 2; am++)
                #pragma unroll
                for (int an = 0; an < 4; an++) {
                    int an16 = an >> 1, hf = an & 1;
                    asm volatile(
                        "mma.sync.aligned.m16n8k16.row.col.f32.f16.f16.f32 "
                        "{%0,%1,%2,%3}, {%4,%5,%6,%7}, {%8,%9}, {%0,%1,%2,%3};"
                        : "+f"(acc[am][an][0]), "+f"(acc[am][an][1]),
                          "+f"(acc[am][an][2]), "+f"(acc[am][an][3])
                        : "r"(a[am][0]), "r"(a[am][1]), "r"(a[am][2]), "r"(a[am][3]),
                          "r"(br[an16][hf * 2]), "r"(br[an16][hf * 2 + 1]));
                }
        }

        // epilogue: g(fp16) = acc * dinv[row]
        __half2* Gh2 = (__half2*)d_g;
        #pragma unroll
        for (int am = 0; am < 2; am++) {
            int r0a = row0 + wm * 32 + am * 16;
            int rA = r0a + g;
            int rB = r0a + g + 8;
            float sA = (rA < NN) ? d_dinv[rA] : 0.0f;
            float sB = (rB < NN) ? d_dinv[rB] : 0.0f;
            #pragma unroll
            for (int an = 0; an < 4; an++) {
                int col = wn * 32 + an * 8 + 2 * t;
                if (rA < NN)
                    Gh2[(size_t)rA * 64 + (col >> 1)] =
                        __floats2half2_rn(acc[am][an][0] * sA, acc[am][an][1] * sA);
                if (rB < NN)
                    Gh2[(size_t)rB * 64 + (col >> 1)] =
                        __floats2half2_rn(acc[am][an][2] * sB, acc[am][an][3] * sB);
            }
        }
        __syncthreads();
        tt = nxt;
    }
}

// ---------------- aggregation: fp16 gather + HADD2 accumulate ------------------
// Lane covers 4 cols = 2 half2 = one uint2 (8B). Zero converts in the loop.
__global__ __launch_bounds__(256) void aggregate_kernel(
    const float* __restrict__ bias, int relu, int outsel)
{
    int node = blockIdx.x * 8 + (threadIdx.x >> 5);
    if (node >= NN) return;
    int lane = threadIdx.x & 31;
    __half* out = (outsel == 1) ? d_h0 : d_h1;

    const uint2* g2 = (const uint2*)d_g;
    uint2 su = g2[(size_t)node * 32 + lane];     // self term
    __half2 a01 = *(__half2*)&su.x;
    __half2 a23 = *(__half2*)&su.y;

    int s = d_rowptr[node], e = d_rowptr[node + 1];
    int j = s;
    for (; j + 3 < e; j += 4) {
        int s0 = d_esrc[j], s1 = d_esrc[j + 1], s2 = d_esrc[j + 2], s3 = d_esrc[j + 3];
        uint2 u0 = g2[(size_t)s0 * 32 + lane];
        uint2 u1 = g2[(size_t)s1 * 32 + lane];
        uint2 u2 = g2[(size_t)s2 * 32 + lane];
        uint2 u3 = g2[(size_t)s3 * 32 + lane];
        __half2 p01 = __hadd2(__hadd2(*(__half2*)&u0.x, *(__half2*)&u1.x),
                              __hadd2(*(__half2*)&u2.x, *(__half2*)&u3.x));
        __half2 p23 = __hadd2(__hadd2(*(__half2*)&u0.y, *(__half2*)&u1.y),
                              __hadd2(*(__half2*)&u2.y, *(__half2*)&u3.y));
        a01 = __hadd2(a01, p01);
        a23 = __hadd2(a23, p23);
    }
    for (; j < e; j++) {
        uint2 u = g2[(size_t)d_esrc[j] * 32 + lane];
        a01 = __hadd2(a01, *(__half2*)&u.x);
        a23 = __hadd2(a23, *(__half2*)&u.y);
    }

    float2 f01 = __half22float2(a01);
    float2 f23 = __half22float2(a23);
    float di = d_dinv[node];
    float4 b4 = ((const float4*)bias)[lane];
    float ox = fmaf(f01.x, di, b4.x);
    float oy = fmaf(f01.y, di, b4.y);
    float oz = fmaf(f23.x, di, b4.z);
    float ow = fmaf(f23.y, di, b4.w);
    if (relu) {
        ox = fmaxf(ox, 0.f); oy = fmaxf(oy, 0.f);
        oz = fmaxf(oz, 0.f); ow = fmaxf(ow, 0.f);
    }
    uint2 ov;
    ov.x = packh2(ox, oy);
    ov.y = packh2(oz, ow);
    ((uint2*)out)[(size_t)node * 32 + lane] = ov;
}

// ---------------- fused last-hop aggregation + classifier + pool ----------------
__global__ __launch_bounds__(256) void aggregate_cls_kernel(
    const float* __restrict__ bias, const int* __restrict__ batch,
    const float* __restrict__ Wc, const float* __restrict__ bc)
{
    __shared__ float sW[HH * OUTD];
    __shared__ float sB[OUTD];
    int tid = threadIdx.x;
    for (int i = tid; i < HH * OUTD; i += 256) sW[i] = Wc[i];
    if (tid < OUTD) sB[tid] = bc[tid];
    __syncthreads();

    int node = blockIdx.x * 8 + (tid >> 5);
    if (node >= NN) return;
    int lane = tid & 31;

    const uint2* g2 = (const uint2*)d_g;
    uint2 su = g2[(size_t)node * 32 + lane];
    __half2 a01 = *(__half2*)&su.x;
    __half2 a23 = *(__half2*)&su.y;

    int s = d_rowptr[node], e = d_rowptr[node + 1];
    int j = s;
    for (; j + 3 < e; j += 4) {
        int s0 = d_esrc[j], s1 = d_esrc[j + 1], s2 = d_esrc[j + 2], s3 = d_esrc[j + 3];
        uint2 u0 = g2[(size_t)s0 * 32 + lane];
        uint2 u1 = g2[(size_t)s1 * 32 + lane];
        uint2 u2 = g2[(size_t)s2 * 32 + lane];
        uint2 u3 = g2[(size_t)s3 * 32 + lane];
        __half2 p01 = __hadd2(__hadd2(*(__half2*)&u0.x, *(__half2*)&u1.x),
                              __hadd2(*(__half2*)&u2.x, *(__half2*)&u3.x));
        __half2 p23 = __hadd2(__hadd2(*(__half2*)&u0.y, *(__half2*)&u1.y),
                              __hadd2(*(__half2*)&u2.y, *(__half2*)&u3.y));
        a01 = __hadd2(a01, p01);
        a23 = __hadd2(a23, p23);
    }
    for (; j < e; j++) {
        uint2 u = g2[(size_t)d_esrc[j] * 32 + lane];
        a01 = __hadd2(a01, *(__half2*)&u.x);
        a23 = __hadd2(a23, *(__half2*)&u.y);
    }

    float2 f01 = __half22float2(a01);
    float2 f23 = __half22float2(a23);
    float di = d_dinv[node];
    float4 b4 = ((const float4*)bias)[lane];
    float ox = fmaf(f01.x, di, b4.x);
    float oy = fmaf(f01.y, di, b4.y);
    float oz = fmaf(f23.x, di, b4.z);
    float ow = fmaf(f23.y, di, b4.w);

    int c0 = 4 * lane;
    float p[OUTD];
    #pragma unroll
    for (int d = 0; d < OUTD; d++) {
        float v = ox * sW[(c0 + 0) * OUTD + d];
        v = fmaf(oy, sW[(c0 + 1) * OUTD + d], v);
        v = fmaf(oz, sW[(c0 + 2) * OUTD + d], v);
        v = fmaf(ow, sW[(c0 + 3) * OUTD + d], v);
        p[d] = v;
    }
    #pragma unroll
    for (int off = 16; off > 0; off >>= 1) {
        #pragma unroll
        for (int d = 0; d < OUTD; d++)
            p[d] += __shfl_xor_sync(0xffffffffu, p[d], off);
    }
    int st = d_stride;
    int b = clampi(batch[(size_t)st * node], 0, GG - 1);
    if (lane < OUTD) {
        float v = p[0];
        #pragma unroll
        for (int d = 1; d < OUTD; d++) v = (lane == d) ? p[d] : v;
        atomicAdd(&d_sums[b * OUTD + lane], v + sB[lane]);
    }
    if (lane == OUTD) atomicAdd(&d_cnt[b], 1.0f);
}

// ---------------- final divide ----------------
__global__ void finalize_kernel(float* __restrict__ out) {
    int i = blockIdx.x * blockDim.x + threadIdx.x;
    if (i < GG * OUTD) {
        float c = d_cnt[i / OUTD];
        out[i] = d_sums[i] / fmaxf(c, 1.0f);
    }
}

// ---------------- launch ----------------
extern "C" void kernel_launch(void* const* d_in, const int* in_sizes, int n_in,
                              void* d_out, int out_size) {
    const float* x      = (const float*)d_in[0];
    const int*   ei     = (const int*)d_in[1];
    const int*   batch  = (const int*)d_in[2];
    const float* W_in   = (const float*)d_in[3];
    const float* b_in   = (const float*)d_in[4];
    const float* W_hops = (const float*)d_in[5];
    const float* b_hops = (const float*)d_in[6];
    const float* W_cls  = (const float*)d_in[7];
    const float* b_cls  = (const float*)d_in[8];
    float* out = (float*)d_out;

    detect_kernel<<<1, 128>>>(ei);
    zero_kernel<<<(NN + 255) / 256, 256>>>();
    count_kernel<<<(EE + 255) / 256, 256>>>(ei);
    // encoder GEMM in slot 4 for stable ncu sampling (writes fp16 h0)
    gemm_enc_kernel<<<GEMM_GRID, 256>>>(x, W_in, b_in, 1);
    scanA_kernel<<<NB, 256>>>();
    scanB_kernel<<<1, 256>>>();
    scanC_kernel<<<NB, 256>>>();
    scatter_kernel<<<(EE + 255) / 256, 256>>>(ei);

    int cur = 1;   // d_h0
    for (int hop = 0; hop < NHOPS; hop++) {
        int nxt = (cur == 1) ? 2 : 1;
        gemm_hop_kernel<<<GEMM_GRID, 256>>>(W_hops + (size_t)hop * HH * HH, cur);
        if (hop < NHOPS - 1) {
            aggregate_kernel<<<(NN + 7) / 8, 256>>>(b_hops + hop * HH, 1, nxt);
        } else {
            aggregate_cls_kernel<<<(NN + 7) / 8, 256>>>(b_hops + hop * HH,
                                                        batch, W_cls, b_cls);
        }
        cur = nxt;
    }

    finalize_kernel<<<(GG * OUTD + 255) / 256, 256>>>(out);
}